// round 7
// baseline (speedup 1.0000x reference)
#include <cuda_runtime.h>
#include <cstdint>
#include <math.h>

#define T_TOK 2048
#define D_EMB 1024
#define H_EXP 2048
#define N_EXP 8

#define KS 32          // fp32 K per stage
#define SW 20          // smem row stride in uint2 (16 data pairs + 4 pad) ; 20 % 16 == 4 -> LDS.64 conflict-free

// ---------------- device scratch (static, allocation-free) ----------------
__device__ __align__(16) int   g_cnt[N_EXP];
__device__ __align__(16) int   g_pair[N_EXP * T_TOK];   // pair id = t*2 + k
__device__ __align__(16) float g_wt [N_EXP * T_TOK];
__device__ __align__(16) float g_act[(size_t)T_TOK * 2 * H_EXP]; // 32 MB
__device__ __align__(16) float g_y  [(size_t)T_TOK * 2 * D_EMB]; // 16 MB

// ---------------- helpers ----------------
__device__ __forceinline__ float gelu_tanh(float x) {
    float x3 = x * x * x;
    float inner = 0.7978845608028654f * (x + 0.044715f * x3);
    return 0.5f * x * (1.0f + tanhf(inner));
}

// fp32 pair (a -> low half / k, b -> high half / k+1) -> bf16x2 hi word + residual lo word
__device__ __forceinline__ void split2(float a, float b, uint32_t& hi, uint32_t& lo) {
    uint32_t h;
    asm("cvt.rn.bf16x2.f32 %0, %1, %2;" : "=r"(h) : "f"(b), "f"(a));
    float ah = __uint_as_float(h << 16);
    float bh = __uint_as_float(h & 0xffff0000u);
    float ar = a - ah, br = b - bh;
    uint32_t l;
    asm("cvt.rn.bf16x2.f32 %0, %1, %2;" : "=r"(l) : "f"(br), "f"(ar));
    hi = h; lo = l;
}

// warp-level bf16 MMA, fp32 accum: D(16x8) += A(16x16) * B(16x8)
__device__ __forceinline__ void hmma(float* c,
                                     uint32_t a0, uint32_t a1, uint32_t a2, uint32_t a3,
                                     uint32_t b0, uint32_t b1) {
    asm volatile(
        "mma.sync.aligned.m16n8k16.row.col.f32.bf16.bf16.f32 "
        "{%0,%1,%2,%3}, {%4,%5,%6,%7}, {%8,%9}, {%0,%1,%2,%3};"
        : "+f"(c[0]), "+f"(c[1]), "+f"(c[2]), "+f"(c[3])
        : "r"(a0), "r"(a1), "r"(a2), "r"(a3), "r"(b0), "r"(b1));
}

// ---------------- small kernels ----------------
__global__ void zero_counts_kernel() {
    if (threadIdx.x < N_EXP) g_cnt[threadIdx.x] = 0;
}

__global__ void gating_kernel(const float* __restrict__ gin,
                              const float* __restrict__ gk,
                              const float* __restrict__ scale) {
    int t = blockIdx.x;
    const float* row = gin + (size_t)t * D_EMB;
    float p[N_EXP];
#pragma unroll
    for (int e = 0; e < N_EXP; e++) p[e] = 0.0f;
    for (int i = threadIdx.x; i < D_EMB; i += blockDim.x) {
        float v = row[i];
#pragma unroll
        for (int e = 0; e < N_EXP; e++) p[e] += v * gk[i * N_EXP + e];
    }
#pragma unroll
    for (int e = 0; e < N_EXP; e++) {
#pragma unroll
        for (int off = 16; off > 0; off >>= 1)
            p[e] += __shfl_down_sync(0xffffffffu, p[e], off);
    }
    __shared__ float sm[8][N_EXP];
    int warp = threadIdx.x >> 5, lane = threadIdx.x & 31;
    if (lane == 0) {
#pragma unroll
        for (int e = 0; e < N_EXP; e++) sm[warp][e] = p[e];
    }
    __syncthreads();
    if (threadIdx.x == 0) {
        float logit[N_EXP];
        int nw = blockDim.x >> 5;
#pragma unroll
        for (int e = 0; e < N_EXP; e++) {
            float s = 0.0f;
            for (int w = 0; w < nw; w++) s += sm[w][e];
            logit[e] = s;
        }
        int e0 = 0;
#pragma unroll
        for (int e = 1; e < N_EXP; e++) if (logit[e] > logit[e0]) e0 = e;
        int e1 = (e0 == 0) ? 1 : 0;
#pragma unroll
        for (int e = 0; e < N_EXP; e++)
            if (e != e0 && logit[e] > logit[e1]) e1 = e;
        float w0 = (1.0f / (1.0f + expf(-logit[e0]))) * scale[e0];
        float w1 = (1.0f / (1.0f + expf(-logit[e1]))) * scale[e1];
        int s0 = atomicAdd(&g_cnt[e0], 1);
        g_pair[e0 * T_TOK + s0] = t * 2 + 0; g_wt[e0 * T_TOK + s0] = w0;
        int s1 = atomicAdd(&g_cnt[e1], 1);
        g_pair[e1 * T_TOK + s1] = t * 2 + 1; g_wt[e1 * T_TOK + s1] = w1;
    }
}

// SMEM layout (uint2 units): A: [2 bufs][128*SW]; B tiles: [2 bufs][64*SW]
#define A_BUF_SZ   (128 * SW)
#define B_BUF_SZ   (64 * SW)
#define UP_SMEM_B  ((2 * A_BUF_SZ + 4 * B_BUF_SZ) * 8)     // 81920 bytes
#define DN_SMEM_B  ((2 * A_BUF_SZ + 2 * B_BUF_SZ) * 8)     // 61440 bytes

// ---------------- pass 1: HMMA bf16x3 fused gate/up ----------------
// CTA: 256 thr (8 warps: wm=wid&3, wn=wid>>2). Tile M128 x N64, warp 32x32.
__global__ __launch_bounds__(256, 2)
void moe_up_mma(const float* __restrict__ x,
                const float* __restrict__ wg,
                const float* __restrict__ wu) {
    int e = blockIdx.z;
    int cnt = g_cnt[e];
    int m0 = blockIdx.y * 128;
    if (m0 >= cnt) return;
    int n0 = blockIdx.x * 64;

    extern __shared__ uint2 smem_u2[];
    uint2* sA  = smem_u2;                       // 2 * A_BUF_SZ
    uint2* sBg = smem_u2 + 2 * A_BUF_SZ;        // 2 * B_BUF_SZ
    uint2* sBu = sBg + 2 * B_BUF_SZ;            // 2 * B_BUF_SZ
    __shared__ int srow[128];

    int tid = threadIdx.x, lane = tid & 31, wid = tid >> 5;
    int wm = wid & 3, wn = wid >> 2;

    if (tid < 128) {
        int s = m0 + tid;
        srow[tid] = (s < cnt) ? g_pair[e * T_TOK + s] : -1;
    }
    __syncthreads();

    const float* wge = wg + (size_t)e * D_EMB * H_EXP;
    const float* wue = wu + (size_t)e * D_EMB * H_EXP;

    // B loader mapping (conflict-free STS): 256 thr -> 2 matrices x (8 bbk x 16 bbn)
    int bmat = tid >> 7, br = tid & 127;
    int bbk = br & 7, bbn = (br >> 3) & 15;
    const float* wsel = bmat ? wue : wge;
    uint2* dB = bmat ? sBu : sBg;

    // A loader mapping: idx -> row = idx>>3, q = idx&7 (word-pair index)
    float acc_g[2][4][4], acc_u[2][4][4];
#pragma unroll
    for (int i = 0; i < 2; i++)
#pragma unroll
        for (int j = 0; j < 4; j++)
#pragma unroll
            for (int q = 0; q < 4; q++) { acc_g[i][j][q] = 0.f; acc_u[i][j][q] = 0.f; }

    float4 pa[4], pb[4];

#define UP_LOAD(K0) { \
    _Pragma("unroll") \
    for (int it = 0; it < 4; it++) { \
        int idx = it * 256 + tid, row = idx >> 3, q = idx & 7; \
        int pr = srow[row]; \
        pa[it] = (pr >= 0) ? __ldg((const float4*)(x + (size_t)(pr >> 1) * D_EMB + (K0) + q * 4)) \
                           : make_float4(0.f, 0.f, 0.f, 0.f); \
    } \
    const float* src = wsel + (size_t)((K0) + bbk * 4) * H_EXP + n0 + bbn * 4; \
    pb[0] = __ldg((const float4*)src); \
    pb[1] = __ldg((const float4*)(src + H_EXP)); \
    pb[2] = __ldg((const float4*)(src + 2 * H_EXP)); \
    pb[3] = __ldg((const float4*)(src + 3 * H_EXP)); }

#define UP_CONVERT(BUF) { \
    uint2* aT = sA + (BUF) * A_BUF_SZ; \
    _Pragma("unroll") \
    for (int it = 0; it < 4; it++) { \
        int idx = it * 256 + tid, row = idx >> 3, q = idx & 7; \
        uint32_t h0, l0, h1, l1; \
        split2(pa[it].x, pa[it].y, h0, l0); \
        split2(pa[it].z, pa[it].w, h1, l1); \
        *(uint4*)&aT[row * SW + 2 * q] = make_uint4(h0, l0, h1, l1); \
    } \
    uint2* bT = dB + (BUF) * B_BUF_SZ; \
    _Pragma("unroll") \
    for (int J = 0; J < 4; J++) { \
        float v0 = (&pb[0].x)[J], v1 = (&pb[1].x)[J]; \
        float v2 = (&pb[2].x)[J], v3 = (&pb[3].x)[J]; \
        uint32_t h0, l0, h1, l1; \
        split2(v0, v1, h0, l0); \
        split2(v2, v3, h1, l1); \
        *(uint4*)&bT[(bbn * 4 + J) * SW + 2 * bbk] = make_uint4(h0, l0, h1, l1); \
    } }

    UP_LOAD(0)
    UP_CONVERT(0)
    UP_LOAD(KS)

    const int S = D_EMB / KS;   // 32
#pragma unroll 1
    for (int s = 0; s < S; s++) {
        __syncthreads();
        if (s + 1 < S) UP_CONVERT((s + 1) & 1)
        if (s + 2 < S) UP_LOAD((s + 2) * KS)

        const uint2* aT = sA + (s & 1) * A_BUF_SZ;
        const uint2* gT = sBg + (s & 1) * B_BUF_SZ;
        const uint2* uT = sBu + (s & 1) * B_BUF_SZ;
#pragma unroll
        for (int ks = 0; ks < 2; ks++) {
            int c = ks * 8 + (lane & 3);
            uint32_t ah[2][4], al[2][4];
#pragma unroll
            for (int ma = 0; ma < 2; ma++) {
                int r = wm * 32 + ma * 16 + (lane >> 2);
                uint2 p0 = aT[r * SW + c];
                uint2 p1 = aT[(r + 8) * SW + c];
                uint2 p2 = aT[r * SW + c + 4];
                uint2 p3 = aT[(r + 8) * SW + c + 4];
                ah[ma][0] = p0.x; al[ma][0] = p0.y;
                ah[ma][1] = p1.x; al[ma][1] = p1.y;
                ah[ma][2] = p2.x; al[ma][2] = p2.y;
                ah[ma][3] = p3.x; al[ma][3] = p3.y;
            }
#pragma unroll
            for (int na = 0; na < 4; na++) {
                int n = wn * 32 + na * 8 + (lane >> 2);
                uint2 qg0 = gT[n * SW + c], qg1 = gT[n * SW + c + 4];
                uint2 qu0 = uT[n * SW + c], qu1 = uT[n * SW + c + 4];
#pragma unroll
                for (int ma = 0; ma < 2; ma++) {
                    hmma(acc_g[ma][na], ah[ma][0], ah[ma][1], ah[ma][2], ah[ma][3], qg0.x, qg1.x);
                    hmma(acc_g[ma][na], al[ma][0], al[ma][1], al[ma][2], al[ma][3], qg0.x, qg1.x);
                    hmma(acc_g[ma][na], ah[ma][0], ah[ma][1], ah[ma][2], ah[ma][3], qg0.y, qg1.y);
                    hmma(acc_u[ma][na], ah[ma][0], ah[ma][1], ah[ma][2], ah[ma][3], qu0.x, qu1.x);
                    hmma(acc_u[ma][na], al[ma][0], al[ma][1], al[ma][2], al[ma][3], qu0.x, qu1.x);
                    hmma(acc_u[ma][na], ah[ma][0], ah[ma][1], ah[ma][2], ah[ma][3], qu0.y, qu1.y);
                }
            }
        }
    }

    // ---- epilogue: act = gelu(gate) * up ----
#pragma unroll
    for (int ma = 0; ma < 2; ma++) {
        int row0 = wm * 32 + ma * 16 + (lane >> 2);
#pragma unroll
        for (int half = 0; half < 2; half++) {
            int row = row0 + half * 8;
            int pr = srow[row];
            if (pr < 0) continue;
            float* dst = g_act + (size_t)pr * H_EXP + n0;
#pragma unroll
            for (int na = 0; na < 4; na++) {
                float g0 = acc_g[ma][na][half * 2 + 0], g1 = acc_g[ma][na][half * 2 + 1];
                float u0 = acc_u[ma][na][half * 2 + 0], u1 = acc_u[ma][na][half * 2 + 1];
                int col = wn * 32 + na * 8 + (lane & 3) * 2;
                *(float2*)(dst + col) = make_float2(gelu_tanh(g0) * u0, gelu_tanh(g1) * u1);
            }
        }
    }
#undef UP_LOAD
#undef UP_CONVERT
}

// ---------------- pass 2: HMMA bf16x3 down-proj ----------------
__global__ __launch_bounds__(256, 2)
void moe_down_mma(const float* __restrict__ wd) {
    int e = blockIdx.z;
    int cnt = g_cnt[e];
    int m0 = blockIdx.y * 128;
    if (m0 >= cnt) return;
    int n0 = blockIdx.x * 64;

    extern __shared__ uint2 smem_u2[];
    uint2* sA = smem_u2;                    // 2 * A_BUF_SZ
    uint2* sB = smem_u2 + 2 * A_BUF_SZ;     // 2 * B_BUF_SZ
    __shared__ int   srow[128];
    __shared__ float swt[128];

    int tid = threadIdx.x, lane = tid & 31, wid = tid >> 5;
    int wm = wid & 3, wn = wid >> 2;

    if (tid < 128) {
        int s = m0 + tid;
        if (s < cnt) { srow[tid] = g_pair[e * T_TOK + s]; swt[tid] = g_wt[e * T_TOK + s]; }
        else         { srow[tid] = -1; swt[tid] = 0.f; }
    }
    __syncthreads();

    const float* wde = wd + (size_t)e * H_EXP * D_EMB;

    int bbk = tid & 7, bbn = (tid >> 3) & 15;
    bool bload = (tid < 128);

    float acc[2][4][4];
#pragma unroll
    for (int i = 0; i < 2; i++)
#pragma unroll
        for (int j = 0; j < 4; j++)
#pragma unroll
            for (int q = 0; q < 4; q++) acc[i][j][q] = 0.f;

    float4 pa[4], pb[4];

#define DN_LOAD(K0) { \
    _Pragma("unroll") \
    for (int it = 0; it < 4; it++) { \
        int idx = it * 256 + tid, row = idx >> 3, q = idx & 7; \
        int pr = srow[row]; \
        pa[it] = (pr >= 0) ? __ldg((const float4*)(g_act + (size_t)pr * H_EXP + (K0) + q * 4)) \
                           : make_float4(0.f, 0.f, 0.f, 0.f); \
    } \
    if (bload) { \
        const float* src = wde + (size_t)((K0) + bbk * 4) * D_EMB + n0 + bbn * 4; \
        pb[0] = __ldg((const float4*)src); \
        pb[1] = __ldg((const float4*)(src + D_EMB)); \
        pb[2] = __ldg((const float4*)(src + 2 * D_EMB)); \
        pb[3] = __ldg((const float4*)(src + 3 * D_EMB)); \
    } }

#define DN_CONVERT(BUF) { \
    uint2* aT = sA + (BUF) * A_BUF_SZ; \
    _Pragma("unroll") \
    for (int it = 0; it < 4; it++) { \
        int idx = it * 256 + tid, row = idx >> 3, q = idx & 7; \
        uint32_t h0, l0, h1, l1; \
        split2(pa[it].x, pa[it].y, h0, l0); \
        split2(pa[it].z, pa[it].w, h1, l1); \
        *(uint4*)&aT[row * SW + 2 * q] = make_uint4(h0, l0, h1, l1); \
    } \
    if (bload) { \
        uint2* bT = sB + (BUF) * B_BUF_SZ; \
        _Pragma("unroll") \
        for (int J = 0; J < 4; J++) { \
            float v0 = (&pb[0].x)[J], v1 = (&pb[1].x)[J]; \
            float v2 = (&pb[2].x)[J], v3 = (&pb[3].x)[J]; \
            uint32_t h0, l0, h1, l1; \
            split2(v0, v1, h0, l0); \
            split2(v2, v3, h1, l1); \
            *(uint4*)&bT[(bbn * 4 + J) * SW + 2 * bbk] = make_uint4(h0, l0, h1, l1); \
        } \
    } }

    DN_LOAD(0)
    DN_CONVERT(0)
    DN_LOAD(KS)

    const int S = H_EXP / KS;   // 64
#pragma unroll 1
    for (int s = 0; s < S; s++) {
        __syncthreads();
        if (s + 1 < S) DN_CONVERT((s + 1) & 1)
        if (s + 2 < S) DN_LOAD((s + 2) * KS)

        const uint2* aT = sA + (s & 1) * A_BUF_SZ;
        const uint2* bT = sB + (s & 1) * B_BUF_SZ;
#pragma unroll
        for (int ks = 0; ks < 2; ks++) {
            int c = ks * 8 + (lane & 3);
            uint32_t ah[2][4], al[2][4];
#pragma unroll
            for (int ma = 0; ma < 2; ma++) {
                int r = wm * 32 + ma * 16 + (lane >> 2);
                uint2 p0 = aT[r * SW + c];
                uint2 p1 = aT[(r + 8) * SW + c];
                uint2 p2 = aT[r * SW + c + 4];
                uint2 p3 = aT[(r + 8) * SW + c + 4];
                ah[ma][0] = p0.x; al[ma][0] = p0.y;
                ah[ma][1] = p1.x; al[ma][1] = p1.y;
                ah[ma][2] = p2.x; al[ma][2] = p2.y;
                ah[ma][3] = p3.x; al[ma][3] = p3.y;
            }
#pragma unroll
            for (int na = 0; na < 4; na++) {
                int n = wn * 32 + na * 8 + (lane >> 2);
                uint2 q0 = bT[n * SW + c], q1 = bT[n * SW + c + 4];
#pragma unroll
                for (int ma = 0; ma < 2; ma++) {
                    hmma(acc[ma][na], ah[ma][0], ah[ma][1], ah[ma][2], ah[ma][3], q0.x, q1.x);
                    hmma(acc[ma][na], al[ma][0], al[ma][1], al[ma][2], al[ma][3], q0.x, q1.x);
                    hmma(acc[ma][na], ah[ma][0], ah[ma][1], ah[ma][2], ah[ma][3], q0.y, q1.y);
                }
            }
        }
    }

#pragma unroll
    for (int ma = 0; ma < 2; ma++) {
        int row0 = wm * 32 + ma * 16 + (lane >> 2);
#pragma unroll
        for (int half = 0; half < 2; half++) {
            int row = row0 + half * 8;
            int pr = srow[row];
            if (pr < 0) continue;
            float w = swt[row];
            float* dst = g_y + (size_t)pr * D_EMB + n0;
#pragma unroll
            for (int na = 0; na < 4; na++) {
                float v0 = acc[ma][na][half * 2 + 0] * w;
                float v1 = acc[ma][na][half * 2 + 1] * w;
                int col = wn * 32 + na * 8 + (lane & 3) * 2;
                *(float2*)(dst + col) = make_float2(v0, v1);
            }
        }
    }
#undef DN_LOAD
#undef DN_CONVERT
}

// ---------------- combine ----------------
__global__ void combine_kernel(float* __restrict__ out) {
    size_t i = (size_t)blockIdx.x * blockDim.x + threadIdx.x;
    int t = (int)(i >> 10);
    int d = (int)(i & 1023);
    out[i] = g_y[(size_t)t * 2048 + d] + g_y[(size_t)t * 2048 + 1024 + d];
}

// ---------------- launch ----------------
extern "C" void kernel_launch(void* const* d_in, const int* in_sizes, int n_in,
                              void* d_out, int out_size) {
    const float* x     = (const float*)d_in[0];
    const float* gin   = (const float*)d_in[1];
    const float* gk    = (const float*)d_in[2];
    const float* scale = (const float*)d_in[3];
    const float* wg    = (const float*)d_in[4];
    const float* wu    = (const float*)d_in[5];
    const float* wd    = (const float*)d_in[6];
    float* out         = (float*)d_out;

    cudaFuncSetAttribute(moe_up_mma,   cudaFuncAttributeMaxDynamicSharedMemorySize, UP_SMEM_B);
    cudaFuncSetAttribute(moe_down_mma, cudaFuncAttributeMaxDynamicSharedMemorySize, DN_SMEM_B);

    zero_counts_kernel<<<1, 32>>>();
    gating_kernel<<<T_TOK, 256>>>(gin, gk, scale);

    dim3 g1(H_EXP / 64, T_TOK / 128, N_EXP);   // 32 x 16 x 8 (early exit on empty m-tiles)
    moe_up_mma<<<g1, 256, UP_SMEM_B>>>(x, wg, wu);

    dim3 g2(D_EMB / 64, T_TOK / 128, N_EXP);   // 16 x 16 x 8
    moe_down_mma<<<g2, 256, DN_SMEM_B>>>(wd);

    combine_kernel<<<(T_TOK * D_EMB) / 256, 256>>>(out);
}

// round 8
// speedup vs baseline: 1.0002x; 1.0002x over previous
#include <cuda_runtime.h>
#include <cstdint>
#include <math.h>

#define T_TOK 2048
#define D_EMB 1024
#define H_EXP 2048
#define N_EXP 8

#define KS 32          // fp32 K per stage
#define SW 20          // smem row stride in uint2 (16 data pairs + 4 pad) ; 20 % 16 == 4 -> LDS.64 conflict-free

// ---------------- device scratch (static, allocation-free) ----------------
__device__ __align__(16) int   g_cnt[N_EXP];
__device__ __align__(16) int   g_pair[N_EXP * T_TOK];   // pair id = t*2 + k
__device__ __align__(16) float g_wt [N_EXP * T_TOK];
__device__ __align__(16) float g_act[(size_t)T_TOK * 2 * H_EXP]; // 32 MB
__device__ __align__(16) float g_y  [(size_t)T_TOK * 2 * D_EMB]; // 16 MB

// ---------------- helpers ----------------
__device__ __forceinline__ float gelu_tanh(float x) {
    float x3 = x * x * x;
    float inner = 0.7978845608028654f * (x + 0.044715f * x3);
    return 0.5f * x * (1.0f + tanhf(inner));
}

// fp32 pair (a -> low half / k, b -> high half / k+1) -> bf16x2 hi word + residual lo word
__device__ __forceinline__ void split2(float a, float b, uint32_t& hi, uint32_t& lo) {
    uint32_t h;
    asm("cvt.rn.bf16x2.f32 %0, %1, %2;" : "=r"(h) : "f"(b), "f"(a));
    float ah = __uint_as_float(h << 16);
    float bh = __uint_as_float(h & 0xffff0000u);
    float ar = a - ah, br = b - bh;
    uint32_t l;
    asm("cvt.rn.bf16x2.f32 %0, %1, %2;" : "=r"(l) : "f"(br), "f"(ar));
    hi = h; lo = l;
}

// warp-level bf16 MMA, fp32 accum: D(16x8) += A(16x16) * B(16x8)
__device__ __forceinline__ void hmma(float* c,
                                     uint32_t a0, uint32_t a1, uint32_t a2, uint32_t a3,
                                     uint32_t b0, uint32_t b1) {
    asm volatile(
        "mma.sync.aligned.m16n8k16.row.col.f32.bf16.bf16.f32 "
        "{%0,%1,%2,%3}, {%4,%5,%6,%7}, {%8,%9}, {%0,%1,%2,%3};"
        : "+f"(c[0]), "+f"(c[1]), "+f"(c[2]), "+f"(c[3])
        : "r"(a0), "r"(a1), "r"(a2), "r"(a3), "r"(b0), "r"(b1));
}

// ---------------- small kernels ----------------
__global__ void zero_counts_kernel() {
    if (threadIdx.x < N_EXP) g_cnt[threadIdx.x] = 0;
}

__global__ void gating_kernel(const float* __restrict__ gin,
                              const float* __restrict__ gk,
                              const float* __restrict__ scale) {
    int t = blockIdx.x;
    const float* row = gin + (size_t)t * D_EMB;
    float p[N_EXP];
#pragma unroll
    for (int e = 0; e < N_EXP; e++) p[e] = 0.0f;
    for (int i = threadIdx.x; i < D_EMB; i += blockDim.x) {
        float v = row[i];
#pragma unroll
        for (int e = 0; e < N_EXP; e++) p[e] += v * gk[i * N_EXP + e];
    }
#pragma unroll
    for (int e = 0; e < N_EXP; e++) {
#pragma unroll
        for (int off = 16; off > 0; off >>= 1)
            p[e] += __shfl_down_sync(0xffffffffu, p[e], off);
    }
    __shared__ float sm[8][N_EXP];
    int warp = threadIdx.x >> 5, lane = threadIdx.x & 31;
    if (lane == 0) {
#pragma unroll
        for (int e = 0; e < N_EXP; e++) sm[warp][e] = p[e];
    }
    __syncthreads();
    if (threadIdx.x == 0) {
        float logit[N_EXP];
        int nw = blockDim.x >> 5;
#pragma unroll
        for (int e = 0; e < N_EXP; e++) {
            float s = 0.0f;
            for (int w = 0; w < nw; w++) s += sm[w][e];
            logit[e] = s;
        }
        int e0 = 0;
#pragma unroll
        for (int e = 1; e < N_EXP; e++) if (logit[e] > logit[e0]) e0 = e;
        int e1 = (e0 == 0) ? 1 : 0;
#pragma unroll
        for (int e = 0; e < N_EXP; e++)
            if (e != e0 && logit[e] > logit[e1]) e1 = e;
        float w0 = (1.0f / (1.0f + expf(-logit[e0]))) * scale[e0];
        float w1 = (1.0f / (1.0f + expf(-logit[e1]))) * scale[e1];
        int s0 = atomicAdd(&g_cnt[e0], 1);
        g_pair[e0 * T_TOK + s0] = t * 2 + 0; g_wt[e0 * T_TOK + s0] = w0;
        int s1 = atomicAdd(&g_cnt[e1], 1);
        g_pair[e1 * T_TOK + s1] = t * 2 + 1; g_wt[e1 * T_TOK + s1] = w1;
    }
}

// SMEM layout (uint2 units): A: [2 bufs][128*SW]; B tiles: [2 bufs][64*SW]
#define A_BUF_SZ   (128 * SW)
#define B_BUF_SZ   (64 * SW)
#define UP_SMEM_B  ((2 * A_BUF_SZ + 4 * B_BUF_SZ) * 8)     // 81920 bytes
#define DN_SMEM_B  ((2 * A_BUF_SZ + 2 * B_BUF_SZ) * 8)     // 61440 bytes

// ---------------- pass 1: HMMA bf16x3 fused gate/up ----------------
// CTA: 256 thr (8 warps: wm=wid&3, wn=wid>>2). Tile M128 x N64, warp 32x32.
__global__ __launch_bounds__(256, 2)
void moe_up_mma(const float* __restrict__ x,
                const float* __restrict__ wg,
                const float* __restrict__ wu) {
    int e = blockIdx.z;
    int cnt = g_cnt[e];
    int m0 = blockIdx.y * 128;
    if (m0 >= cnt) return;
    int n0 = blockIdx.x * 64;

    extern __shared__ uint2 smem_u2[];
    uint2* sA  = smem_u2;                       // 2 * A_BUF_SZ
    uint2* sBg = smem_u2 + 2 * A_BUF_SZ;        // 2 * B_BUF_SZ
    uint2* sBu = sBg + 2 * B_BUF_SZ;            // 2 * B_BUF_SZ
    __shared__ int srow[128];

    int tid = threadIdx.x, lane = tid & 31, wid = tid >> 5;
    int wm = wid & 3, wn = wid >> 2;

    if (tid < 128) {
        int s = m0 + tid;
        srow[tid] = (s < cnt) ? g_pair[e * T_TOK + s] : -1;
    }
    __syncthreads();

    const float* wge = wg + (size_t)e * D_EMB * H_EXP;
    const float* wue = wu + (size_t)e * D_EMB * H_EXP;

    // B loader mapping (conflict-free STS): 256 thr -> 2 matrices x (8 bbk x 16 bbn)
    int bmat = tid >> 7, br = tid & 127;
    int bbk = br & 7, bbn = (br >> 3) & 15;
    const float* wsel = bmat ? wue : wge;
    uint2* dB = bmat ? sBu : sBg;

    // A loader mapping: idx -> row = idx>>3, q = idx&7 (word-pair index)
    float acc_g[2][4][4], acc_u[2][4][4];
#pragma unroll
    for (int i = 0; i < 2; i++)
#pragma unroll
        for (int j = 0; j < 4; j++)
#pragma unroll
            for (int q = 0; q < 4; q++) { acc_g[i][j][q] = 0.f; acc_u[i][j][q] = 0.f; }

    float4 pa[4], pb[4];

#define UP_LOAD(K0) { \
    _Pragma("unroll") \
    for (int it = 0; it < 4; it++) { \
        int idx = it * 256 + tid, row = idx >> 3, q = idx & 7; \
        int pr = srow[row]; \
        pa[it] = (pr >= 0) ? __ldg((const float4*)(x + (size_t)(pr >> 1) * D_EMB + (K0) + q * 4)) \
                           : make_float4(0.f, 0.f, 0.f, 0.f); \
    } \
    const float* src = wsel + (size_t)((K0) + bbk * 4) * H_EXP + n0 + bbn * 4; \
    pb[0] = __ldg((const float4*)src); \
    pb[1] = __ldg((const float4*)(src + H_EXP)); \
    pb[2] = __ldg((const float4*)(src + 2 * H_EXP)); \
    pb[3] = __ldg((const float4*)(src + 3 * H_EXP)); }

#define UP_CONVERT(BUF) { \
    uint2* aT = sA + (BUF) * A_BUF_SZ; \
    _Pragma("unroll") \
    for (int it = 0; it < 4; it++) { \
        int idx = it * 256 + tid, row = idx >> 3, q = idx & 7; \
        uint32_t h0, l0, h1, l1; \
        split2(pa[it].x, pa[it].y, h0, l0); \
        split2(pa[it].z, pa[it].w, h1, l1); \
        *(uint4*)&aT[row * SW + 2 * q] = make_uint4(h0, l0, h1, l1); \
    } \
    uint2* bT = dB + (BUF) * B_BUF_SZ; \
    _Pragma("unroll") \
    for (int J = 0; J < 4; J++) { \
        float v0 = (&pb[0].x)[J], v1 = (&pb[1].x)[J]; \
        float v2 = (&pb[2].x)[J], v3 = (&pb[3].x)[J]; \
        uint32_t h0, l0, h1, l1; \
        split2(v0, v1, h0, l0); \
        split2(v2, v3, h1, l1); \
        *(uint4*)&bT[(bbn * 4 + J) * SW + 2 * bbk] = make_uint4(h0, l0, h1, l1); \
    } }

    UP_LOAD(0)
    UP_CONVERT(0)
    UP_LOAD(KS)

    const int S = D_EMB / KS;   // 32
#pragma unroll 1
    for (int s = 0; s < S; s++) {
        __syncthreads();
        if (s + 1 < S) UP_CONVERT((s + 1) & 1)
        if (s + 2 < S) UP_LOAD((s + 2) * KS)

        const uint2* aT = sA + (s & 1) * A_BUF_SZ;
        const uint2* gT = sBg + (s & 1) * B_BUF_SZ;
        const uint2* uT = sBu + (s & 1) * B_BUF_SZ;
#pragma unroll
        for (int ks = 0; ks < 2; ks++) {
            int c = ks * 8 + (lane & 3);
            uint32_t ah[2][4], al[2][4];
#pragma unroll
            for (int ma = 0; ma < 2; ma++) {
                int r = wm * 32 + ma * 16 + (lane >> 2);
                uint2 p0 = aT[r * SW + c];
                uint2 p1 = aT[(r + 8) * SW + c];
                uint2 p2 = aT[r * SW + c + 4];
                uint2 p3 = aT[(r + 8) * SW + c + 4];
                ah[ma][0] = p0.x; al[ma][0] = p0.y;
                ah[ma][1] = p1.x; al[ma][1] = p1.y;
                ah[ma][2] = p2.x; al[ma][2] = p2.y;
                ah[ma][3] = p3.x; al[ma][3] = p3.y;
            }
#pragma unroll
            for (int na = 0; na < 4; na++) {
                int n = wn * 32 + na * 8 + (lane >> 2);
                uint2 qg0 = gT[n * SW + c], qg1 = gT[n * SW + c + 4];
                uint2 qu0 = uT[n * SW + c], qu1 = uT[n * SW + c + 4];
#pragma unroll
                for (int ma = 0; ma < 2; ma++) {
                    hmma(acc_g[ma][na], ah[ma][0], ah[ma][1], ah[ma][2], ah[ma][3], qg0.x, qg1.x);
                    hmma(acc_g[ma][na], al[ma][0], al[ma][1], al[ma][2], al[ma][3], qg0.x, qg1.x);
                    hmma(acc_g[ma][na], ah[ma][0], ah[ma][1], ah[ma][2], ah[ma][3], qg0.y, qg1.y);
                    hmma(acc_u[ma][na], ah[ma][0], ah[ma][1], ah[ma][2], ah[ma][3], qu0.x, qu1.x);
                    hmma(acc_u[ma][na], al[ma][0], al[ma][1], al[ma][2], al[ma][3], qu0.x, qu1.x);
                    hmma(acc_u[ma][na], ah[ma][0], ah[ma][1], ah[ma][2], ah[ma][3], qu0.y, qu1.y);
                }
            }
        }
    }

    // ---- epilogue: act = gelu(gate) * up ----
#pragma unroll
    for (int ma = 0; ma < 2; ma++) {
        int row0 = wm * 32 + ma * 16 + (lane >> 2);
#pragma unroll
        for (int half = 0; half < 2; half++) {
            int row = row0 + half * 8;
            int pr = srow[row];
            if (pr < 0) continue;
            float* dst = g_act + (size_t)pr * H_EXP + n0;
#pragma unroll
            for (int na = 0; na < 4; na++) {
                float g0 = acc_g[ma][na][half * 2 + 0], g1 = acc_g[ma][na][half * 2 + 1];
                float u0 = acc_u[ma][na][half * 2 + 0], u1 = acc_u[ma][na][half * 2 + 1];
                int col = wn * 32 + na * 8 + (lane & 3) * 2;
                *(float2*)(dst + col) = make_float2(gelu_tanh(g0) * u0, gelu_tanh(g1) * u1);
            }
        }
    }
#undef UP_LOAD
#undef UP_CONVERT
}

// ---------------- pass 2: HMMA bf16x3 down-proj ----------------
__global__ __launch_bounds__(256, 2)
void moe_down_mma(const float* __restrict__ wd) {
    int e = blockIdx.z;
    int cnt = g_cnt[e];
    int m0 = blockIdx.y * 128;
    if (m0 >= cnt) return;
    int n0 = blockIdx.x * 64;

    extern __shared__ uint2 smem_u2[];
    uint2* sA = smem_u2;                    // 2 * A_BUF_SZ
    uint2* sB = smem_u2 + 2 * A_BUF_SZ;     // 2 * B_BUF_SZ
    __shared__ int   srow[128];
    __shared__ float swt[128];

    int tid = threadIdx.x, lane = tid & 31, wid = tid >> 5;
    int wm = wid & 3, wn = wid >> 2;

    if (tid < 128) {
        int s = m0 + tid;
        if (s < cnt) { srow[tid] = g_pair[e * T_TOK + s]; swt[tid] = g_wt[e * T_TOK + s]; }
        else         { srow[tid] = -1; swt[tid] = 0.f; }
    }
    __syncthreads();

    const float* wde = wd + (size_t)e * H_EXP * D_EMB;

    int bbk = tid & 7, bbn = (tid >> 3) & 15;
    bool bload = (tid < 128);

    float acc[2][4][4];
#pragma unroll
    for (int i = 0; i < 2; i++)
#pragma unroll
        for (int j = 0; j < 4; j++)
#pragma unroll
            for (int q = 0; q < 4; q++) acc[i][j][q] = 0.f;

    float4 pa[4], pb[4];

#define DN_LOAD(K0) { \
    _Pragma("unroll") \
    for (int it = 0; it < 4; it++) { \
        int idx = it * 256 + tid, row = idx >> 3, q = idx & 7; \
        int pr = srow[row]; \
        pa[it] = (pr >= 0) ? __ldg((const float4*)(g_act + (size_t)pr * H_EXP + (K0) + q * 4)) \
                           : make_float4(0.f, 0.f, 0.f, 0.f); \
    } \
    if (bload) { \
        const float* src = wde + (size_t)((K0) + bbk * 4) * D_EMB + n0 + bbn * 4; \
        pb[0] = __ldg((const float4*)src); \
        pb[1] = __ldg((const float4*)(src + D_EMB)); \
        pb[2] = __ldg((const float4*)(src + 2 * D_EMB)); \
        pb[3] = __ldg((const float4*)(src + 3 * D_EMB)); \
    } }

#define DN_CONVERT(BUF) { \
    uint2* aT = sA + (BUF) * A_BUF_SZ; \
    _Pragma("unroll") \
    for (int it = 0; it < 4; it++) { \
        int idx = it * 256 + tid, row = idx >> 3, q = idx & 7; \
        uint32_t h0, l0, h1, l1; \
        split2(pa[it].x, pa[it].y, h0, l0); \
        split2(pa[it].z, pa[it].w, h1, l1); \
        *(uint4*)&aT[row * SW + 2 * q] = make_uint4(h0, l0, h1, l1); \
    } \
    if (bload) { \
        uint2* bT = sB + (BUF) * B_BUF_SZ; \
        _Pragma("unroll") \
        for (int J = 0; J < 4; J++) { \
            float v0 = (&pb[0].x)[J], v1 = (&pb[1].x)[J]; \
            float v2 = (&pb[2].x)[J], v3 = (&pb[3].x)[J]; \
            uint32_t h0, l0, h1, l1; \
            split2(v0, v1, h0, l0); \
            split2(v2, v3, h1, l1); \
            *(uint4*)&bT[(bbn * 4 + J) * SW + 2 * bbk] = make_uint4(h0, l0, h1, l1); \
        } \
    } }

    DN_LOAD(0)
    DN_CONVERT(0)
    DN_LOAD(KS)

    const int S = H_EXP / KS;   // 64
#pragma unroll 1
    for (int s = 0; s < S; s++) {
        __syncthreads();
        if (s + 1 < S) DN_CONVERT((s + 1) & 1)
        if (s + 2 < S) DN_LOAD((s + 2) * KS)

        const uint2* aT = sA + (s & 1) * A_BUF_SZ;
        const uint2* bT = sB + (s & 1) * B_BUF_SZ;
#pragma unroll
        for (int ks = 0; ks < 2; ks++) {
            int c = ks * 8 + (lane & 3);
            uint32_t ah[2][4], al[2][4];
#pragma unroll
            for (int ma = 0; ma < 2; ma++) {
                int r = wm * 32 + ma * 16 + (lane >> 2);
                uint2 p0 = aT[r * SW + c];
                uint2 p1 = aT[(r + 8) * SW + c];
                uint2 p2 = aT[r * SW + c + 4];
                uint2 p3 = aT[(r + 8) * SW + c + 4];
                ah[ma][0] = p0.x; al[ma][0] = p0.y;
                ah[ma][1] = p1.x; al[ma][1] = p1.y;
                ah[ma][2] = p2.x; al[ma][2] = p2.y;
                ah[ma][3] = p3.x; al[ma][3] = p3.y;
            }
#pragma unroll
            for (int na = 0; na < 4; na++) {
                int n = wn * 32 + na * 8 + (lane >> 2);
                uint2 q0 = bT[n * SW + c], q1 = bT[n * SW + c + 4];
#pragma unroll
                for (int ma = 0; ma < 2; ma++) {
                    hmma(acc[ma][na], ah[ma][0], ah[ma][1], ah[ma][2], ah[ma][3], q0.x, q1.x);
                    hmma(acc[ma][na], al[ma][0], al[ma][1], al[ma][2], al[ma][3], q0.x, q1.x);
                    hmma(acc[ma][na], ah[ma][0], ah[ma][1], ah[ma][2], ah[ma][3], q0.y, q1.y);
                }
            }
        }
    }

#pragma unroll
    for (int ma = 0; ma < 2; ma++) {
        int row0 = wm * 32 + ma * 16 + (lane >> 2);
#pragma unroll
        for (int half = 0; half < 2; half++) {
            int row = row0 + half * 8;
            int pr = srow[row];
            if (pr < 0) continue;
            float w = swt[row];
            float* dst = g_y + (size_t)pr * D_EMB + n0;
#pragma unroll
            for (int na = 0; na < 4; na++) {
                float v0 = acc[ma][na][half * 2 + 0] * w;
                float v1 = acc[ma][na][half * 2 + 1] * w;
                int col = wn * 32 + na * 8 + (lane & 3) * 2;
                *(float2*)(dst + col) = make_float2(v0, v1);
            }
        }
    }
#undef DN_LOAD
#undef DN_CONVERT
}

// ---------------- combine ----------------
__global__ void combine_kernel(float* __restrict__ out) {
    size_t i = (size_t)blockIdx.x * blockDim.x + threadIdx.x;
    int t = (int)(i >> 10);
    int d = (int)(i & 1023);
    out[i] = g_y[(size_t)t * 2048 + d] + g_y[(size_t)t * 2048 + 1024 + d];
}

// ---------------- launch ----------------
extern "C" void kernel_launch(void* const* d_in, const int* in_sizes, int n_in,
                              void* d_out, int out_size) {
    const float* x     = (const float*)d_in[0];
    const float* gin   = (const float*)d_in[1];
    const float* gk    = (const float*)d_in[2];
    const float* scale = (const float*)d_in[3];
    const float* wg    = (const float*)d_in[4];
    const float* wu    = (const float*)d_in[5];
    const float* wd    = (const float*)d_in[6];
    float* out         = (float*)d_out;

    cudaFuncSetAttribute(moe_up_mma,   cudaFuncAttributeMaxDynamicSharedMemorySize, UP_SMEM_B);
    cudaFuncSetAttribute(moe_down_mma, cudaFuncAttributeMaxDynamicSharedMemorySize, DN_SMEM_B);

    zero_counts_kernel<<<1, 32>>>();
    gating_kernel<<<T_TOK, 256>>>(gin, gk, scale);

    dim3 g1(H_EXP / 64, T_TOK / 128, N_EXP);   // 32 x 16 x 8 (early exit on empty m-tiles)
    moe_up_mma<<<g1, 256, UP_SMEM_B>>>(x, wg, wu);

    dim3 g2(D_EMB / 64, T_TOK / 128, N_EXP);   // 16 x 16 x 8
    moe_down_mma<<<g2, 256, DN_SMEM_B>>>(wd);

    combine_kernel<<<(T_TOK * D_EMB) / 256, 256>>>(out);
}

// round 9
// speedup vs baseline: 1.2389x; 1.2387x over previous
#include <cuda_runtime.h>
#include <cstdint>
#include <math.h>

#define T_TOK 2048
#define D_EMB 1024
#define H_EXP 2048
#define N_EXP 8

#define KS  32          // fp32 K per stage
#define SWW 40          // uint32 words per smem row (32 data + 8 pad)
#define A_WORDS (128 * SWW)
#define B_WORDS (64 * SWW)

// ---------------- device scratch (static, allocation-free) ----------------
__device__ __align__(16) int   g_cnt[N_EXP];
__device__ __align__(16) int   g_pair[N_EXP * T_TOK];   // pair id = t*2 + k
__device__ __align__(16) float g_wt [N_EXP * T_TOK];
__device__ __align__(16) float g_act[(size_t)T_TOK * 2 * H_EXP]; // 32 MB
__device__ __align__(16) float g_y  [(size_t)T_TOK * 2 * D_EMB]; // 16 MB

// ---------------- helpers ----------------
__device__ __forceinline__ float gelu_tanh(float x) {
    float x3 = x * x * x;
    float inner = 0.7978845608028654f * (x + 0.044715f * x3);
    return 0.5f * x * (1.0f + tanhf(inner));
}

__device__ __forceinline__ uint32_t tf32c(float x) {
    uint32_t r;
    asm("cvt.rna.tf32.f32 %0, %1;" : "=r"(r) : "f"(x));
    return r;
}

// D(16x8) += A(16x8) * B(8x8), tf32 operands, fp32 accum
__device__ __forceinline__ void mma_tf32(float* c,
                                         uint32_t a0, uint32_t a1, uint32_t a2, uint32_t a3,
                                         uint32_t b0, uint32_t b1) {
    asm volatile(
        "mma.sync.aligned.m16n8k8.row.col.f32.tf32.tf32.f32 "
        "{%0,%1,%2,%3}, {%4,%5,%6,%7}, {%8,%9}, {%0,%1,%2,%3};"
        : "+f"(c[0]), "+f"(c[1]), "+f"(c[2]), "+f"(c[3])
        : "r"(a0), "r"(a1), "r"(a2), "r"(a3), "r"(b0), "r"(b1));
}

// ---------------- small kernels ----------------
__global__ void zero_counts_kernel() {
    if (threadIdx.x < N_EXP) g_cnt[threadIdx.x] = 0;
}

__global__ void gating_kernel(const float* __restrict__ gin,
                              const float* __restrict__ gk,
                              const float* __restrict__ scale) {
    int t = blockIdx.x;
    const float* row = gin + (size_t)t * D_EMB;
    float p[N_EXP];
#pragma unroll
    for (int e = 0; e < N_EXP; e++) p[e] = 0.0f;
    for (int i = threadIdx.x; i < D_EMB; i += blockDim.x) {
        float v = row[i];
#pragma unroll
        for (int e = 0; e < N_EXP; e++) p[e] += v * gk[i * N_EXP + e];
    }
#pragma unroll
    for (int e = 0; e < N_EXP; e++) {
#pragma unroll
        for (int off = 16; off > 0; off >>= 1)
            p[e] += __shfl_down_sync(0xffffffffu, p[e], off);
    }
    __shared__ float sm[8][N_EXP];
    int warp = threadIdx.x >> 5, lane = threadIdx.x & 31;
    if (lane == 0) {
#pragma unroll
        for (int e = 0; e < N_EXP; e++) sm[warp][e] = p[e];
    }
    __syncthreads();
    if (threadIdx.x == 0) {
        float logit[N_EXP];
        int nw = blockDim.x >> 5;
#pragma unroll
        for (int e = 0; e < N_EXP; e++) {
            float s = 0.0f;
            for (int w = 0; w < nw; w++) s += sm[w][e];
            logit[e] = s;
        }
        int e0 = 0;
#pragma unroll
        for (int e = 1; e < N_EXP; e++) if (logit[e] > logit[e0]) e0 = e;
        int e1 = (e0 == 0) ? 1 : 0;
#pragma unroll
        for (int e = 0; e < N_EXP; e++)
            if (e != e0 && logit[e] > logit[e1]) e1 = e;
        float w0 = (1.0f / (1.0f + expf(-logit[e0]))) * scale[e0];
        float w1 = (1.0f / (1.0f + expf(-logit[e1]))) * scale[e1];
        int s0 = atomicAdd(&g_cnt[e0], 1);
        g_pair[e0 * T_TOK + s0] = t * 2 + 0; g_wt[e0 * T_TOK + s0] = w0;
        int s1 = atomicAdd(&g_cnt[e1], 1);
        g_pair[e1 * T_TOK + s1] = t * 2 + 1; g_wt[e1 * T_TOK + s1] = w1;
    }
}

// SMEM pair layout (per row entity): for kblock kb (0..3), pair m (0..3):
//   words [kb*8 + 2m, kb*8 + 2m + 1] = tf32 values at k = 8kb+m and k = 8kb+m+4.
// Fragment loads become LDS.64 at word kb*8 + 2*(lane&3); row stride 40 -> conflict-free.

// ---------------- pass 1: TF32 fused gate/up ----------------
// CTA: 256 thr, 8 warps (wm = wid&3, wn = wid>>2). Tile M128 x N64, warp 32x32.
__global__ __launch_bounds__(256, 2)
void moe_up_mma(const float* __restrict__ x,
                const float* __restrict__ wg,
                const float* __restrict__ wu) {
    int e = blockIdx.z;
    int cnt = g_cnt[e];
    int m0 = blockIdx.y * 128;
    if (m0 >= cnt) return;
    int n0 = blockIdx.x * 64;

    __shared__ uint32_t sA [A_WORDS];
    __shared__ uint32_t sBg[B_WORDS];
    __shared__ uint32_t sBu[B_WORDS];
    __shared__ int srow[128];

    int tid = threadIdx.x, lane = tid & 31, wid = tid >> 5;
    int wm = wid & 3, wn = wid >> 2;

    if (tid < 128) {
        int s = m0 + tid;
        srow[tid] = (s < cnt) ? g_pair[e * T_TOK + s] : -1;
    }
    __syncthreads();

    const float* wge = wg + (size_t)e * D_EMB * H_EXP;
    const float* wue = wu + (size_t)e * D_EMB * H_EXP;

    // B loader: 256 thr -> 2 matrices x (kb 0..3, mh 0..1, bbn 0..15)
    int bmat = tid >> 7, br = tid & 127;
    int kb_b = br & 3, mh_b = (br >> 2) & 1, bbn = br >> 3;
    const float* wsel = bmat ? wue : wge;
    uint32_t* dB = bmat ? sBu : sBg;
    int brow0 = kb_b * 8 + mh_b * 2;
    int bsto  = kb_b * 8 + mh_b * 4;

    float acc_g[2][4][4], acc_u[2][4][4];
#pragma unroll
    for (int i = 0; i < 2; i++)
#pragma unroll
        for (int j = 0; j < 4; j++)
#pragma unroll
            for (int q = 0; q < 4; q++) { acc_g[i][j][q] = 0.f; acc_u[i][j][q] = 0.f; }

    float2 pa[4][2];
    float4 pb[4];

#define UP_LOAD(K0) { \
    _Pragma("unroll") \
    for (int it = 0; it < 4; it++) { \
        int idx = it * 256 + tid, arow = idx >> 3, sub = idx & 7; \
        int c0 = (sub >> 1) * 8 + (sub & 1) * 2 + (K0); \
        int pr = srow[arow]; \
        if (pr >= 0) { \
            const float* ab = x + (size_t)(pr >> 1) * D_EMB + c0; \
            pa[it][0] = __ldg((const float2*)ab); \
            pa[it][1] = __ldg((const float2*)(ab + 4)); \
        } else { \
            pa[it][0] = make_float2(0.f, 0.f); pa[it][1] = make_float2(0.f, 0.f); \
        } \
    } \
    const float* bsrc = wsel + (size_t)((K0) + brow0) * H_EXP + n0 + bbn * 4; \
    pb[0] = __ldg((const float4*)bsrc); \
    pb[1] = __ldg((const float4*)(bsrc + H_EXP)); \
    pb[2] = __ldg((const float4*)(bsrc + 4 * H_EXP)); \
    pb[3] = __ldg((const float4*)(bsrc + 5 * H_EXP)); }

#define UP_CONVERT() { \
    _Pragma("unroll") \
    for (int it = 0; it < 4; it++) { \
        int idx = it * 256 + tid, arow = idx >> 3, sub = idx & 7; \
        uint4 u = make_uint4(tf32c(pa[it][0].x), tf32c(pa[it][1].x), \
                             tf32c(pa[it][0].y), tf32c(pa[it][1].y)); \
        *(uint4*)&sA[arow * SWW + (sub >> 1) * 8 + (sub & 1) * 4] = u; \
    } \
    _Pragma("unroll") \
    for (int J = 0; J < 4; J++) { \
        uint4 u = make_uint4(tf32c((&pb[0].x)[J]), tf32c((&pb[2].x)[J]), \
                             tf32c((&pb[1].x)[J]), tf32c((&pb[3].x)[J])); \
        *(uint4*)&dB[(bbn * 4 + J) * SWW + bsto] = u; \
    } }

    UP_LOAD(0)

    const int S = D_EMB / KS;   // 32
#pragma unroll 1
    for (int s = 0; s < S; s++) {
        UP_CONVERT()
        __syncthreads();
        if (s + 1 < S) UP_LOAD((s + 1) * KS)

#pragma unroll
        for (int kb = 0; kb < 4; kb++) {
            int cw = kb * 8 + 2 * (lane & 3);
            uint2 a02[2], a13[2];
#pragma unroll
            for (int ma = 0; ma < 2; ma++) {
                int r = wm * 32 + ma * 16 + (lane >> 2);
                a02[ma] = *(const uint2*)&sA[r * SWW + cw];
                a13[ma] = *(const uint2*)&sA[(r + 8) * SWW + cw];
            }
#pragma unroll
            for (int na = 0; na < 4; na++) {
                int n = wn * 32 + na * 8 + (lane >> 2);
                uint2 bg = *(const uint2*)&sBg[n * SWW + cw];
                uint2 bu = *(const uint2*)&sBu[n * SWW + cw];
#pragma unroll
                for (int ma = 0; ma < 2; ma++) {
                    mma_tf32(acc_g[ma][na], a02[ma].x, a13[ma].x, a02[ma].y, a13[ma].y, bg.x, bg.y);
                    mma_tf32(acc_u[ma][na], a02[ma].x, a13[ma].x, a02[ma].y, a13[ma].y, bu.x, bu.y);
                }
            }
        }
        __syncthreads();
    }

    // ---- epilogue: act = gelu(gate) * up ----
#pragma unroll
    for (int ma = 0; ma < 2; ma++) {
        int row0 = wm * 32 + ma * 16 + (lane >> 2);
#pragma unroll
        for (int half = 0; half < 2; half++) {
            int row = row0 + half * 8;
            int pr = srow[row];
            if (pr < 0) continue;
            float* dst = g_act + (size_t)pr * H_EXP + n0;
#pragma unroll
            for (int na = 0; na < 4; na++) {
                float g0 = acc_g[ma][na][half * 2 + 0], g1 = acc_g[ma][na][half * 2 + 1];
                float u0 = acc_u[ma][na][half * 2 + 0], u1 = acc_u[ma][na][half * 2 + 1];
                int col = wn * 32 + na * 8 + (lane & 3) * 2;
                *(float2*)(dst + col) = make_float2(gelu_tanh(g0) * u0, gelu_tanh(g1) * u1);
            }
        }
    }
#undef UP_LOAD
#undef UP_CONVERT
}

// ---------------- pass 2: TF32 down-proj ----------------
__global__ __launch_bounds__(256, 2)
void moe_down_mma(const float* __restrict__ wd) {
    int e = blockIdx.z;
    int cnt = g_cnt[e];
    int m0 = blockIdx.y * 128;
    if (m0 >= cnt) return;
    int n0 = blockIdx.x * 64;

    __shared__ uint32_t sA[A_WORDS];
    __shared__ uint32_t sB[B_WORDS];
    __shared__ int   srow[128];
    __shared__ float swt[128];

    int tid = threadIdx.x, lane = tid & 31, wid = tid >> 5;
    int wm = wid & 3, wn = wid >> 2;

    if (tid < 128) {
        int s = m0 + tid;
        if (s < cnt) { srow[tid] = g_pair[e * T_TOK + s]; swt[tid] = g_wt[e * T_TOK + s]; }
        else         { srow[tid] = -1; swt[tid] = 0.f; }
    }
    __syncthreads();

    const float* wde = wd + (size_t)e * H_EXP * D_EMB;

    bool bload = (tid < 128);
    int kb_b = tid & 3, mh_b = (tid >> 2) & 1, bbn = (tid >> 3) & 15;
    int brow0 = kb_b * 8 + mh_b * 2;
    int bsto  = kb_b * 8 + mh_b * 4;

    float acc[2][4][4];
#pragma unroll
    for (int i = 0; i < 2; i++)
#pragma unroll
        for (int j = 0; j < 4; j++)
#pragma unroll
            for (int q = 0; q < 4; q++) acc[i][j][q] = 0.f;

    float2 pa[4][2];
    float4 pb[4];

#define DN_LOAD(K0) { \
    _Pragma("unroll") \
    for (int it = 0; it < 4; it++) { \
        int idx = it * 256 + tid, arow = idx >> 3, sub = idx & 7; \
        int c0 = (sub >> 1) * 8 + (sub & 1) * 2 + (K0); \
        int pr = srow[arow]; \
        if (pr >= 0) { \
            const float* ab = g_act + (size_t)pr * H_EXP + c0; \
            pa[it][0] = __ldg((const float2*)ab); \
            pa[it][1] = __ldg((const float2*)(ab + 4)); \
        } else { \
            pa[it][0] = make_float2(0.f, 0.f); pa[it][1] = make_float2(0.f, 0.f); \
        } \
    } \
    if (bload) { \
        const float* bsrc = wde + (size_t)((K0) + brow0) * D_EMB + n0 + bbn * 4; \
        pb[0] = __ldg((const float4*)bsrc); \
        pb[1] = __ldg((const float4*)(bsrc + D_EMB)); \
        pb[2] = __ldg((const float4*)(bsrc + 4 * D_EMB)); \
        pb[3] = __ldg((const float4*)(bsrc + 5 * D_EMB)); \
    } }

#define DN_CONVERT() { \
    _Pragma("unroll") \
    for (int it = 0; it < 4; it++) { \
        int idx = it * 256 + tid, arow = idx >> 3, sub = idx & 7; \
        uint4 u = make_uint4(tf32c(pa[it][0].x), tf32c(pa[it][1].x), \
                             tf32c(pa[it][0].y), tf32c(pa[it][1].y)); \
        *(uint4*)&sA[arow * SWW + (sub >> 1) * 8 + (sub & 1) * 4] = u; \
    } \
    if (bload) { \
        _Pragma("unroll") \
        for (int J = 0; J < 4; J++) { \
            uint4 u = make_uint4(tf32c((&pb[0].x)[J]), tf32c((&pb[2].x)[J]), \
                                 tf32c((&pb[1].x)[J]), tf32c((&pb[3].x)[J])); \
            *(uint4*)&sB[(bbn * 4 + J) * SWW + bsto] = u; \
        } \
    } }

    DN_LOAD(0)

    const int S = H_EXP / KS;   // 64
#pragma unroll 1
    for (int s = 0; s < S; s++) {
        DN_CONVERT()
        __syncthreads();
        if (s + 1 < S) DN_LOAD((s + 1) * KS)

#pragma unroll
        for (int kb = 0; kb < 4; kb++) {
            int cw = kb * 8 + 2 * (lane & 3);
            uint2 a02[2], a13[2];
#pragma unroll
            for (int ma = 0; ma < 2; ma++) {
                int r = wm * 32 + ma * 16 + (lane >> 2);
                a02[ma] = *(const uint2*)&sA[r * SWW + cw];
                a13[ma] = *(const uint2*)&sA[(r + 8) * SWW + cw];
            }
#pragma unroll
            for (int na = 0; na < 4; na++) {
                int n = wn * 32 + na * 8 + (lane >> 2);
                uint2 b = *(const uint2*)&sB[n * SWW + cw];
#pragma unroll
                for (int ma = 0; ma < 2; ma++)
                    mma_tf32(acc[ma][na], a02[ma].x, a13[ma].x, a02[ma].y, a13[ma].y, b.x, b.y);
            }
        }
        __syncthreads();
    }

#pragma unroll
    for (int ma = 0; ma < 2; ma++) {
        int row0 = wm * 32 + ma * 16 + (lane >> 2);
#pragma unroll
        for (int half = 0; half < 2; half++) {
            int row = row0 + half * 8;
            int pr = srow[row];
            if (pr < 0) continue;
            float w = swt[row];
            float* dst = g_y + (size_t)pr * D_EMB + n0;
#pragma unroll
            for (int na = 0; na < 4; na++) {
                float v0 = acc[ma][na][half * 2 + 0] * w;
                float v1 = acc[ma][na][half * 2 + 1] * w;
                int col = wn * 32 + na * 8 + (lane & 3) * 2;
                *(float2*)(dst + col) = make_float2(v0, v1);
            }
        }
    }
#undef DN_LOAD
#undef DN_CONVERT
}

// ---------------- combine ----------------
__global__ void combine_kernel(float* __restrict__ out) {
    size_t i = (size_t)blockIdx.x * blockDim.x + threadIdx.x;
    int t = (int)(i >> 10);
    int d = (int)(i & 1023);
    out[i] = g_y[(size_t)t * 2048 + d] + g_y[(size_t)t * 2048 + 1024 + d];
}

// ---------------- launch ----------------
extern "C" void kernel_launch(void* const* d_in, const int* in_sizes, int n_in,
                              void* d_out, int out_size) {
    const float* x     = (const float*)d_in[0];
    const float* gin   = (const float*)d_in[1];
    const float* gk    = (const float*)d_in[2];
    const float* scale = (const float*)d_in[3];
    const float* wg    = (const float*)d_in[4];
    const float* wu    = (const float*)d_in[5];
    const float* wd    = (const float*)d_in[6];
    float* out         = (float*)d_out;

    zero_counts_kernel<<<1, 32>>>();
    gating_kernel<<<T_TOK, 256>>>(gin, gk, scale);

    dim3 g1(H_EXP / 64, T_TOK / 128, N_EXP);   // 32 x 16 x 8 (early exit on empty m-tiles)
    moe_up_mma<<<g1, 256>>>(x, wg, wu);

    dim3 g2(D_EMB / 64, T_TOK / 128, N_EXP);   // 16 x 16 x 8
    moe_down_mma<<<g2, 256>>>(wd);

    combine_kernel<<<(T_TOK * D_EMB) / 256, 256>>>(out);
}

// round 10
// speedup vs baseline: 2.0857x; 1.6835x over previous
#include <cuda_runtime.h>
#include <cstdint>
#include <math.h>

#define T_TOK 2048
#define D_EMB 1024
#define H_EXP 2048
#define N_EXP 8

#define KS 32              // fp32 K per stage
#define ASW 36             // A smem row stride in words (32 data + 4 pad): banks 4r+c -> conflict-free
#define A_BUF (128 * ASW)  // words
#define DBSW 136           // down B row stride ([k][n128], 8k+n banks)
#define DN_BBUF (32 * DBSW)
#define UBSW 72            // up B row stride ([k][n64], 8k+n banks)
#define UP_BBUF (32 * UBSW)
#define DN_SMEM ((2 * A_BUF + 2 * DN_BBUF) * 4)   // 71680 B
#define UP_SMEM ((2 * A_BUF + 4 * UP_BBUF) * 4)   // 73728 B

// ---------------- device scratch (static, allocation-free) ----------------
__device__ __align__(16) int   g_cnt[N_EXP];
__device__ __align__(16) int   g_pair[N_EXP * T_TOK];
__device__ __align__(16) float g_wt [N_EXP * T_TOK];
__device__ __align__(16) float g_act[(size_t)T_TOK * 2 * H_EXP]; // 32 MB
__device__ __align__(16) float g_y  [(size_t)T_TOK * 2 * D_EMB]; // 16 MB

// ---------------- helpers ----------------
__device__ __forceinline__ float gelu_tanh(float x) {
    float x3 = x * x * x;
    float inner = 0.7978845608028654f * (x + 0.044715f * x3);
    return 0.5f * x * (1.0f + tanhf(inner));
}
__device__ __forceinline__ uint32_t tf32c(float x) {
    uint32_t r;
    asm("cvt.rna.tf32.f32 %0, %1;" : "=r"(r) : "f"(x));
    return r;
}
__device__ __forceinline__ void mma_tf32(float* c,
                                         uint32_t a0, uint32_t a1, uint32_t a2, uint32_t a3,
                                         uint32_t b0, uint32_t b1) {
    asm volatile(
        "mma.sync.aligned.m16n8k8.row.col.f32.tf32.tf32.f32 "
        "{%0,%1,%2,%3}, {%4,%5,%6,%7}, {%8,%9}, {%0,%1,%2,%3};"
        : "+f"(c[0]), "+f"(c[1]), "+f"(c[2]), "+f"(c[3])
        : "r"(a0), "r"(a1), "r"(a2), "r"(a3), "r"(b0), "r"(b1));
}
__device__ __forceinline__ void cpa16(uint32_t dst, const void* src) {
    asm volatile("cp.async.cg.shared.global [%0], [%1], 16;" :: "r"(dst), "l"(src));
}
__device__ __forceinline__ void cpa16z(uint32_t dst, const void* src, int sz) {
    asm volatile("cp.async.cg.shared.global [%0], [%1], 16, %2;" :: "r"(dst), "l"(src), "r"(sz));
}
#define CP_COMMIT() asm volatile("cp.async.commit_group;")
#define CP_WAIT1()  asm volatile("cp.async.wait_group 1;")
#define CP_WAIT0()  asm volatile("cp.async.wait_group 0;")

// ---------------- small kernels ----------------
__global__ void zero_counts_kernel() {
    if (threadIdx.x < N_EXP) g_cnt[threadIdx.x] = 0;
}

__global__ void gating_kernel(const float* __restrict__ gin,
                              const float* __restrict__ gk,
                              const float* __restrict__ scale) {
    int t = blockIdx.x;
    const float* row = gin + (size_t)t * D_EMB;
    float p[N_EXP];
#pragma unroll
    for (int e = 0; e < N_EXP; e++) p[e] = 0.0f;
    for (int i = threadIdx.x; i < D_EMB; i += blockDim.x) {
        float v = row[i];
#pragma unroll
        for (int e = 0; e < N_EXP; e++) p[e] += v * gk[i * N_EXP + e];
    }
#pragma unroll
    for (int e = 0; e < N_EXP; e++) {
#pragma unroll
        for (int off = 16; off > 0; off >>= 1)
            p[e] += __shfl_down_sync(0xffffffffu, p[e], off);
    }
    __shared__ float sm[8][N_EXP];
    int warp = threadIdx.x >> 5, lane = threadIdx.x & 31;
    if (lane == 0) {
#pragma unroll
        for (int e = 0; e < N_EXP; e++) sm[warp][e] = p[e];
    }
    __syncthreads();
    if (threadIdx.x == 0) {
        float logit[N_EXP];
        int nw = blockDim.x >> 5;
#pragma unroll
        for (int e = 0; e < N_EXP; e++) {
            float s = 0.0f;
            for (int w = 0; w < nw; w++) s += sm[w][e];
            logit[e] = s;
        }
        int e0 = 0;
#pragma unroll
        for (int e = 1; e < N_EXP; e++) if (logit[e] > logit[e0]) e0 = e;
        int e1 = (e0 == 0) ? 1 : 0;
#pragma unroll
        for (int e = 0; e < N_EXP; e++)
            if (e != e0 && logit[e] > logit[e1]) e1 = e;
        float w0 = (1.0f / (1.0f + expf(-logit[e0]))) * scale[e0];
        float w1 = (1.0f / (1.0f + expf(-logit[e1]))) * scale[e1];
        int s0 = atomicAdd(&g_cnt[e0], 1);
        g_pair[e0 * T_TOK + s0] = t * 2 + 0; g_wt[e0 * T_TOK + s0] = w0;
        int s1 = atomicAdd(&g_cnt[e1], 1);
        g_pair[e1 * T_TOK + s1] = t * 2 + 1; g_wt[e1 * T_TOK + s1] = w1;
    }
}

// ---------------- pass 1: TF32 fused gate/up (cp.async, M128 x N64(x2)) ----------------
// 8 warps: wm = wid&3 (M), wn = wid>>2 (N). warp tile 32 x 32 per matrix.
__global__ __launch_bounds__(256, 2)
void moe_up_mma(const float* __restrict__ x,
                const float* __restrict__ wg,
                const float* __restrict__ wu) {
    int e = blockIdx.z;
    int cnt = g_cnt[e];
    int m0 = blockIdx.y * 128;
    if (m0 >= cnt) return;
    int n0 = blockIdx.x * 64;

    extern __shared__ float dyn[];
    float* fA  = dyn;                        // 2 * A_BUF
    float* fBg = dyn + 2 * A_BUF;            // 2 * UP_BBUF
    float* fBu = fBg + 2 * UP_BBUF;          // 2 * UP_BBUF
    __shared__ int srow[128];

    int tid = threadIdx.x, lane = tid & 31, wid = tid >> 5;
    int wm = wid & 3, wn = wid >> 2;

    if (tid < 128) {
        int s = m0 + tid;
        srow[tid] = (s < cnt) ? g_pair[e * T_TOK + s] : -1;
    }
    __syncthreads();

    uint32_t smA  = (uint32_t)__cvta_generic_to_shared(fA);
    uint32_t smBg = (uint32_t)__cvta_generic_to_shared(fBg);
    uint32_t smBu = (uint32_t)__cvta_generic_to_shared(fBu);

    const float* wge = wg + (size_t)e * D_EMB * H_EXP;
    const float* wue = wu + (size_t)e * D_EMB * H_EXP;

    float acc_g[2][4][4], acc_u[2][4][4];
#pragma unroll
    for (int i = 0; i < 2; i++)
#pragma unroll
        for (int j = 0; j < 4; j++)
#pragma unroll
            for (int q = 0; q < 4; q++) { acc_g[i][j][q] = 0.f; acc_u[i][j][q] = 0.f; }

#define UP_LOAD(S_, BUF_) { \
    int k0 = (S_) * KS; \
    uint32_t ab = smA + (BUF_) * (A_BUF * 4); \
    _Pragma("unroll") \
    for (int it = 0; it < 4; it++) { \
        int ch = it * 256 + tid, row = ch >> 3, off = ch & 7; \
        int pr = srow[row]; \
        const float* src = (pr >= 0) ? x + (size_t)(pr >> 1) * D_EMB + k0 + off * 4 : x; \
        cpa16z(ab + row * (ASW * 4) + off * 16, src, (pr >= 0) ? 16 : 0); \
    } \
    uint32_t gb = smBg + (BUF_) * (UP_BBUF * 4); \
    uint32_t ub = smBu + (BUF_) * (UP_BBUF * 4); \
    _Pragma("unroll") \
    for (int it = 0; it < 4; it++) { \
        int ch = it * 256 + tid; \
        int mat = ch >> 9, k = (ch >> 4) & 31, off = ch & 15; \
        const float* src = (mat ? wue : wge) + (size_t)(k0 + k) * H_EXP + n0 + off * 4; \
        cpa16((mat ? ub : gb) + k * (UBSW * 4) + off * 16, src); \
    } }

    const int S = D_EMB / KS;   // 32
    UP_LOAD(0, 0)
    CP_COMMIT();

#pragma unroll 1
    for (int s = 0; s < S; s++) {
        if (s + 1 < S) { UP_LOAD(s + 1, (s + 1) & 1) CP_COMMIT(); CP_WAIT1(); }
        else           { CP_WAIT0(); }
        __syncthreads();

        const float* aT = fA  + (s & 1) * A_BUF;
        const float* gT = fBg + (s & 1) * UP_BBUF;
        const float* uT = fBu + (s & 1) * UP_BBUF;
#pragma unroll
        for (int kb = 0; kb < 4; kb++) {
            int c = kb * 8 + (lane & 3);
            uint32_t af[2][4];
#pragma unroll
            for (int ma = 0; ma < 2; ma++) {
                int r = wm * 32 + ma * 16 + (lane >> 2);
                af[ma][0] = tf32c(aT[r * ASW + c]);
                af[ma][1] = tf32c(aT[(r + 8) * ASW + c]);
                af[ma][2] = tf32c(aT[r * ASW + c + 4]);
                af[ma][3] = tf32c(aT[(r + 8) * ASW + c + 4]);
            }
#pragma unroll
            for (int na = 0; na < 4; na++) {
                int n = wn * 32 + na * 8 + (lane >> 2);
                uint32_t bg0 = tf32c(gT[c * UBSW + n]);
                uint32_t bg1 = tf32c(gT[(c + 4) * UBSW + n]);
                uint32_t bu0 = tf32c(uT[c * UBSW + n]);
                uint32_t bu1 = tf32c(uT[(c + 4) * UBSW + n]);
#pragma unroll
                for (int ma = 0; ma < 2; ma++) {
                    mma_tf32(acc_g[ma][na], af[ma][0], af[ma][1], af[ma][2], af[ma][3], bg0, bg1);
                    mma_tf32(acc_u[ma][na], af[ma][0], af[ma][1], af[ma][2], af[ma][3], bu0, bu1);
                }
            }
        }
        __syncthreads();
    }

    // epilogue: act = gelu(gate) * up
#pragma unroll
    for (int ma = 0; ma < 2; ma++) {
        int row0 = wm * 32 + ma * 16 + (lane >> 2);
#pragma unroll
        for (int half = 0; half < 2; half++) {
            int row = row0 + half * 8;
            int pr = srow[row];
            if (pr < 0) continue;
            float* dst = g_act + (size_t)pr * H_EXP + n0;
#pragma unroll
            for (int na = 0; na < 4; na++) {
                float g0 = acc_g[ma][na][half * 2 + 0], g1 = acc_g[ma][na][half * 2 + 1];
                float u0 = acc_u[ma][na][half * 2 + 0], u1 = acc_u[ma][na][half * 2 + 1];
                int col = wn * 32 + na * 8 + (lane & 3) * 2;
                *(float2*)(dst + col) = make_float2(gelu_tanh(g0) * u0, gelu_tanh(g1) * u1);
            }
        }
    }
#undef UP_LOAD
}

// ---------------- pass 2: TF32 down-proj (cp.async, M128 x N128) ----------------
// 8 warps: wm = wid&3 (M), wn = wid>>2 (N). warp tile 32 x 64.
__global__ __launch_bounds__(256, 2)
void moe_down_mma(const float* __restrict__ wd) {
    int e = blockIdx.z;
    int cnt = g_cnt[e];
    int m0 = blockIdx.y * 128;
    if (m0 >= cnt) return;
    int n0 = blockIdx.x * 128;

    extern __shared__ float dyn[];
    float* fA = dyn;                 // 2 * A_BUF
    float* fB = dyn + 2 * A_BUF;     // 2 * DN_BBUF
    __shared__ int   srow[128];
    __shared__ float swt[128];

    int tid = threadIdx.x, lane = tid & 31, wid = tid >> 5;
    int wm = wid & 3, wn = wid >> 2;

    if (tid < 128) {
        int s = m0 + tid;
        if (s < cnt) { srow[tid] = g_pair[e * T_TOK + s]; swt[tid] = g_wt[e * T_TOK + s]; }
        else         { srow[tid] = -1; swt[tid] = 0.f; }
    }
    __syncthreads();

    uint32_t smA = (uint32_t)__cvta_generic_to_shared(fA);
    uint32_t smB = (uint32_t)__cvta_generic_to_shared(fB);

    const float* wde = wd + (size_t)e * H_EXP * D_EMB;

    float acc[2][8][4];
#pragma unroll
    for (int i = 0; i < 2; i++)
#pragma unroll
        for (int j = 0; j < 8; j++)
#pragma unroll
            for (int q = 0; q < 4; q++) acc[i][j][q] = 0.f;

#define DN_LOAD(S_, BUF_) { \
    int k0 = (S_) * KS; \
    uint32_t ab = smA + (BUF_) * (A_BUF * 4); \
    _Pragma("unroll") \
    for (int it = 0; it < 4; it++) { \
        int ch = it * 256 + tid, row = ch >> 3, off = ch & 7; \
        int pr = srow[row]; \
        const float* src = (pr >= 0) ? g_act + (size_t)pr * H_EXP + k0 + off * 4 : g_act; \
        cpa16z(ab + row * (ASW * 4) + off * 16, src, (pr >= 0) ? 16 : 0); \
    } \
    uint32_t bb = smB + (BUF_) * (DN_BBUF * 4); \
    _Pragma("unroll") \
    for (int it = 0; it < 4; it++) { \
        int ch = it * 256 + tid, k = ch >> 5, off = ch & 31; \
        cpa16(bb + k * (DBSW * 4) + off * 16, \
              wde + (size_t)(k0 + k) * D_EMB + n0 + off * 4); \
    } }

    const int S = H_EXP / KS;   // 64
    DN_LOAD(0, 0)
    CP_COMMIT();

#pragma unroll 1
    for (int s = 0; s < S; s++) {
        if (s + 1 < S) { DN_LOAD(s + 1, (s + 1) & 1) CP_COMMIT(); CP_WAIT1(); }
        else           { CP_WAIT0(); }
        __syncthreads();

        const float* aT = fA + (s & 1) * A_BUF;
        const float* bT = fB + (s & 1) * DN_BBUF;
#pragma unroll
        for (int kb = 0; kb < 4; kb++) {
            int c = kb * 8 + (lane & 3);
            uint32_t af[2][4];
#pragma unroll
            for (int ma = 0; ma < 2; ma++) {
                int r = wm * 32 + ma * 16 + (lane >> 2);
                af[ma][0] = tf32c(aT[r * ASW + c]);
                af[ma][1] = tf32c(aT[(r + 8) * ASW + c]);
                af[ma][2] = tf32c(aT[r * ASW + c + 4]);
                af[ma][3] = tf32c(aT[(r + 8) * ASW + c + 4]);
            }
#pragma unroll
            for (int na = 0; na < 8; na++) {
                int n = wn * 64 + na * 8 + (lane >> 2);
                uint32_t b0 = tf32c(bT[c * DBSW + n]);
                uint32_t b1 = tf32c(bT[(c + 4) * DBSW + n]);
#pragma unroll
                for (int ma = 0; ma < 2; ma++)
                    mma_tf32(acc[ma][na], af[ma][0], af[ma][1], af[ma][2], af[ma][3], b0, b1);
            }
        }
        __syncthreads();
    }

#pragma unroll
    for (int ma = 0; ma < 2; ma++) {
        int row0 = wm * 32 + ma * 16 + (lane >> 2);
#pragma unroll
        for (int half = 0; half < 2; half++) {
            int row = row0 + half * 8;
            int pr = srow[row];
            if (pr < 0) continue;
            float w = swt[row];
            float* dst = g_y + (size_t)pr * D_EMB + n0;
#pragma unroll
            for (int na = 0; na < 8; na++) {
                float v0 = acc[ma][na][half * 2 + 0] * w;
                float v1 = acc[ma][na][half * 2 + 1] * w;
                int col = wn * 64 + na * 8 + (lane & 3) * 2;
                *(float2*)(dst + col) = make_float2(v0, v1);
            }
        }
    }
#undef DN_LOAD
}

// ---------------- combine ----------------
__global__ void combine_kernel(float* __restrict__ out) {
    size_t i = (size_t)blockIdx.x * blockDim.x + threadIdx.x;
    int t = (int)(i >> 10);
    int d = (int)(i & 1023);
    out[i] = g_y[(size_t)t * 2048 + d] + g_y[(size_t)t * 2048 + 1024 + d];
}

// ---------------- launch ----------------
extern "C" void kernel_launch(void* const* d_in, const int* in_sizes, int n_in,
                              void* d_out, int out_size) {
    const float* x     = (const float*)d_in[0];
    const float* gin   = (const float*)d_in[1];
    const float* gk    = (const float*)d_in[2];
    const float* scale = (const float*)d_in[3];
    const float* wg    = (const float*)d_in[4];
    const float* wu    = (const float*)d_in[5];
    const float* wd    = (const float*)d_in[6];
    float* out         = (float*)d_out;

    cudaFuncSetAttribute(moe_up_mma,   cudaFuncAttributeMaxDynamicSharedMemorySize, UP_SMEM);
    cudaFuncSetAttribute(moe_down_mma, cudaFuncAttributeMaxDynamicSharedMemorySize, DN_SMEM);

    zero_counts_kernel<<<1, 32>>>();
    gating_kernel<<<T_TOK, 256>>>(gin, gk, scale);

    dim3 g1(H_EXP / 64, T_TOK / 128, N_EXP);    // 32 x 16 x 8
    moe_up_mma<<<g1, 256, UP_SMEM>>>(x, wg, wu);

    dim3 g2(D_EMB / 128, T_TOK / 128, N_EXP);   // 8 x 16 x 8
    moe_down_mma<<<g2, 256, DN_SMEM>>>(wd);

    combine_kernel<<<(T_TOK * D_EMB) / 256, 256>>>(out);
}

// round 11
// speedup vs baseline: 2.0900x; 1.0020x over previous
#include <cuda_runtime.h>
#include <cstdint>
#include <math.h>

#define T_TOK 2048
#define D_EMB 1024
#define H_EXP 2048
#define N_EXP 8

#define KS 32              // fp32 K per stage
#define ASW 36             // A smem row stride in words (32 data + 4 pad): banks 4r+c -> conflict-free
#define A_BUF (128 * ASW)  // words
#define DBSW 136           // down B row stride ([k][n128], 8k+n banks)
#define DN_BBUF (32 * DBSW)
#define UBSW 72            // up B row stride ([k][n64], 8k+n banks)
#define UP_BBUF (32 * UBSW)
#define DN_SMEM ((2 * A_BUF + 2 * DN_BBUF) * 4)   // 71680 B
#define UP_SMEM ((2 * A_BUF + 4 * UP_BBUF) * 4)   // 73728 B

// ---------------- device scratch (static, allocation-free) ----------------
__device__ __align__(16) int   g_cnt[N_EXP];
__device__ __align__(16) int   g_pair[N_EXP * T_TOK];
__device__ __align__(16) float g_wt [N_EXP * T_TOK];
__device__ __align__(16) float g_act[(size_t)T_TOK * 2 * H_EXP]; // 32 MB
__device__ __align__(16) float g_y  [(size_t)T_TOK * 2 * D_EMB]; // 16 MB

// ---------------- helpers ----------------
__device__ __forceinline__ float gelu_tanh(float x) {
    float x3 = x * x * x;
    float inner = 0.7978845608028654f * (x + 0.044715f * x3);
    return 0.5f * x * (1.0f + tanhf(inner));
}
__device__ __forceinline__ uint32_t tf32c(float x) {
    uint32_t r;
    asm("cvt.rna.tf32.f32 %0, %1;" : "=r"(r) : "f"(x));
    return r;
}
__device__ __forceinline__ void mma_tf32(float* c,
                                         uint32_t a0, uint32_t a1, uint32_t a2, uint32_t a3,
                                         uint32_t b0, uint32_t b1) {
    asm volatile(
        "mma.sync.aligned.m16n8k8.row.col.f32.tf32.tf32.f32 "
        "{%0,%1,%2,%3}, {%4,%5,%6,%7}, {%8,%9}, {%0,%1,%2,%3};"
        : "+f"(c[0]), "+f"(c[1]), "+f"(c[2]), "+f"(c[3])
        : "r"(a0), "r"(a1), "r"(a2), "r"(a3), "r"(b0), "r"(b1));
}
__device__ __forceinline__ void cpa16(uint32_t dst, const void* src) {
    asm volatile("cp.async.cg.shared.global [%0], [%1], 16;" :: "r"(dst), "l"(src));
}
__device__ __forceinline__ void cpa16z(uint32_t dst, const void* src, int sz) {
    asm volatile("cp.async.cg.shared.global [%0], [%1], 16, %2;" :: "r"(dst), "l"(src), "r"(sz));
}
#define CP_COMMIT() asm volatile("cp.async.commit_group;")
#define CP_WAIT1()  asm volatile("cp.async.wait_group 1;")
#define CP_WAIT0()  asm volatile("cp.async.wait_group 0;")

// ---------------- small kernels ----------------
__global__ void zero_counts_kernel() {
    if (threadIdx.x < N_EXP) g_cnt[threadIdx.x] = 0;
}

__global__ void gating_kernel(const float* __restrict__ gin,
                              const float* __restrict__ gk,
                              const float* __restrict__ scale) {
    int t = blockIdx.x;
    const float* row = gin + (size_t)t * D_EMB;
    float p[N_EXP];
#pragma unroll
    for (int e = 0; e < N_EXP; e++) p[e] = 0.0f;
    for (int i = threadIdx.x; i < D_EMB; i += blockDim.x) {
        float v = row[i];
#pragma unroll
        for (int e = 0; e < N_EXP; e++) p[e] += v * gk[i * N_EXP + e];
    }
#pragma unroll
    for (int e = 0; e < N_EXP; e++) {
#pragma unroll
        for (int off = 16; off > 0; off >>= 1)
            p[e] += __shfl_down_sync(0xffffffffu, p[e], off);
    }
    __shared__ float sm[8][N_EXP];
    int warp = threadIdx.x >> 5, lane = threadIdx.x & 31;
    if (lane == 0) {
#pragma unroll
        for (int e = 0; e < N_EXP; e++) sm[warp][e] = p[e];
    }
    __syncthreads();
    if (threadIdx.x == 0) {
        float logit[N_EXP];
        int nw = blockDim.x >> 5;
#pragma unroll
        for (int e = 0; e < N_EXP; e++) {
            float s = 0.0f;
            for (int w = 0; w < nw; w++) s += sm[w][e];
            logit[e] = s;
        }
        int e0 = 0;
#pragma unroll
        for (int e = 1; e < N_EXP; e++) if (logit[e] > logit[e0]) e0 = e;
        int e1 = (e0 == 0) ? 1 : 0;
#pragma unroll
        for (int e = 0; e < N_EXP; e++)
            if (e != e0 && logit[e] > logit[e1]) e1 = e;
        float w0 = (1.0f / (1.0f + expf(-logit[e0]))) * scale[e0];
        float w1 = (1.0f / (1.0f + expf(-logit[e1]))) * scale[e1];
        int s0 = atomicAdd(&g_cnt[e0], 1);
        g_pair[e0 * T_TOK + s0] = t * 2 + 0; g_wt[e0 * T_TOK + s0] = w0;
        int s1 = atomicAdd(&g_cnt[e1], 1);
        g_pair[e1 * T_TOK + s1] = t * 2 + 1; g_wt[e1 * T_TOK + s1] = w1;
    }
}

// ---------------- pass 1: TF32 fused gate/up (cp.async, M128 x N64(x2)) ----------------
// 8 warps: wm = wid&3 (M), wn = wid>>2 (N). warp tile 32 x 32 per matrix.
__global__ __launch_bounds__(256, 2)
void moe_up_mma(const float* __restrict__ x,
                const float* __restrict__ wg,
                const float* __restrict__ wu) {
    int e = blockIdx.z;
    int cnt = g_cnt[e];
    int m0 = blockIdx.y * 128;
    if (m0 >= cnt) return;
    int n0 = blockIdx.x * 64;

    extern __shared__ float dyn[];
    float* fA  = dyn;                        // 2 * A_BUF
    float* fBg = dyn + 2 * A_BUF;            // 2 * UP_BBUF
    float* fBu = fBg + 2 * UP_BBUF;          // 2 * UP_BBUF
    __shared__ int srow[128];

    int tid = threadIdx.x, lane = tid & 31, wid = tid >> 5;
    int wm = wid & 3, wn = wid >> 2;

    if (tid < 128) {
        int s = m0 + tid;
        srow[tid] = (s < cnt) ? g_pair[e * T_TOK + s] : -1;
    }
    __syncthreads();

    uint32_t smA  = (uint32_t)__cvta_generic_to_shared(fA);
    uint32_t smBg = (uint32_t)__cvta_generic_to_shared(fBg);
    uint32_t smBu = (uint32_t)__cvta_generic_to_shared(fBu);

    const float* wge = wg + (size_t)e * D_EMB * H_EXP;
    const float* wue = wu + (size_t)e * D_EMB * H_EXP;

    float acc_g[2][4][4], acc_u[2][4][4];
#pragma unroll
    for (int i = 0; i < 2; i++)
#pragma unroll
        for (int j = 0; j < 4; j++)
#pragma unroll
            for (int q = 0; q < 4; q++) { acc_g[i][j][q] = 0.f; acc_u[i][j][q] = 0.f; }

#define UP_LOAD(S_, BUF_) { \
    int k0 = (S_) * KS; \
    uint32_t ab = smA + (BUF_) * (A_BUF * 4); \
    _Pragma("unroll") \
    for (int it = 0; it < 4; it++) { \
        int ch = it * 256 + tid, row = ch >> 3, off = ch & 7; \
        int pr = srow[row]; \
        const float* src = (pr >= 0) ? x + (size_t)(pr >> 1) * D_EMB + k0 + off * 4 : x; \
        cpa16z(ab + row * (ASW * 4) + off * 16, src, (pr >= 0) ? 16 : 0); \
    } \
    uint32_t gb = smBg + (BUF_) * (UP_BBUF * 4); \
    uint32_t ub = smBu + (BUF_) * (UP_BBUF * 4); \
    _Pragma("unroll") \
    for (int it = 0; it < 4; it++) { \
        int ch = it * 256 + tid; \
        int mat = ch >> 9, k = (ch >> 4) & 31, off = ch & 15; \
        const float* src = (mat ? wue : wge) + (size_t)(k0 + k) * H_EXP + n0 + off * 4; \
        cpa16((mat ? ub : gb) + k * (UBSW * 4) + off * 16, src); \
    } }

    const int S = D_EMB / KS;   // 32
    UP_LOAD(0, 0)
    CP_COMMIT();

#pragma unroll 1
    for (int s = 0; s < S; s++) {
        if (s + 1 < S) { UP_LOAD(s + 1, (s + 1) & 1) CP_COMMIT(); CP_WAIT1(); }
        else           { CP_WAIT0(); }
        __syncthreads();

        const float* aT = fA  + (s & 1) * A_BUF;
        const float* gT = fBg + (s & 1) * UP_BBUF;
        const float* uT = fBu + (s & 1) * UP_BBUF;
#pragma unroll
        for (int kb = 0; kb < 4; kb++) {
            int c = kb * 8 + (lane & 3);
            uint32_t af[2][4];
#pragma unroll
            for (int ma = 0; ma < 2; ma++) {
                int r = wm * 32 + ma * 16 + (lane >> 2);
                af[ma][0] = tf32c(aT[r * ASW + c]);
                af[ma][1] = tf32c(aT[(r + 8) * ASW + c]);
                af[ma][2] = tf32c(aT[r * ASW + c + 4]);
                af[ma][3] = tf32c(aT[(r + 8) * ASW + c + 4]);
            }
#pragma unroll
            for (int na = 0; na < 4; na++) {
                int n = wn * 32 + na * 8 + (lane >> 2);
                uint32_t bg0 = tf32c(gT[c * UBSW + n]);
                uint32_t bg1 = tf32c(gT[(c + 4) * UBSW + n]);
                uint32_t bu0 = tf32c(uT[c * UBSW + n]);
                uint32_t bu1 = tf32c(uT[(c + 4) * UBSW + n]);
#pragma unroll
                for (int ma = 0; ma < 2; ma++) {
                    mma_tf32(acc_g[ma][na], af[ma][0], af[ma][1], af[ma][2], af[ma][3], bg0, bg1);
                    mma_tf32(acc_u[ma][na], af[ma][0], af[ma][1], af[ma][2], af[ma][3], bu0, bu1);
                }
            }
        }
        __syncthreads();
    }

    // epilogue: act = gelu(gate) * up
#pragma unroll
    for (int ma = 0; ma < 2; ma++) {
        int row0 = wm * 32 + ma * 16 + (lane >> 2);
#pragma unroll
        for (int half = 0; half < 2; half++) {
            int row = row0 + half * 8;
            int pr = srow[row];
            if (pr < 0) continue;
            float* dst = g_act + (size_t)pr * H_EXP + n0;
#pragma unroll
            for (int na = 0; na < 4; na++) {
                float g0 = acc_g[ma][na][half * 2 + 0], g1 = acc_g[ma][na][half * 2 + 1];
                float u0 = acc_u[ma][na][half * 2 + 0], u1 = acc_u[ma][na][half * 2 + 1];
                int col = wn * 32 + na * 8 + (lane & 3) * 2;
                *(float2*)(dst + col) = make_float2(gelu_tanh(g0) * u0, gelu_tanh(g1) * u1);
            }
        }
    }
#undef UP_LOAD
}

// ---------------- pass 2: TF32 down-proj (cp.async, M128 x N128) ----------------
// 8 warps: wm = wid&3 (M), wn = wid>>2 (N). warp tile 32 x 64.
__global__ __launch_bounds__(256, 2)
void moe_down_mma(const float* __restrict__ wd) {
    int e = blockIdx.z;
    int cnt = g_cnt[e];
    int m0 = blockIdx.y * 128;
    if (m0 >= cnt) return;
    int n0 = blockIdx.x * 128;

    extern __shared__ float dyn[];
    float* fA = dyn;                 // 2 * A_BUF
    float* fB = dyn + 2 * A_BUF;     // 2 * DN_BBUF
    __shared__ int   srow[128];
    __shared__ float swt[128];

    int tid = threadIdx.x, lane = tid & 31, wid = tid >> 5;
    int wm = wid & 3, wn = wid >> 2;

    if (tid < 128) {
        int s = m0 + tid;
        if (s < cnt) { srow[tid] = g_pair[e * T_TOK + s]; swt[tid] = g_wt[e * T_TOK + s]; }
        else         { srow[tid] = -1; swt[tid] = 0.f; }
    }
    __syncthreads();

    uint32_t smA = (uint32_t)__cvta_generic_to_shared(fA);
    uint32_t smB = (uint32_t)__cvta_generic_to_shared(fB);

    const float* wde = wd + (size_t)e * H_EXP * D_EMB;

    float acc[2][8][4];
#pragma unroll
    for (int i = 0; i < 2; i++)
#pragma unroll
        for (int j = 0; j < 8; j++)
#pragma unroll
            for (int q = 0; q < 4; q++) acc[i][j][q] = 0.f;

#define DN_LOAD(S_, BUF_) { \
    int k0 = (S_) * KS; \
    uint32_t ab = smA + (BUF_) * (A_BUF * 4); \
    _Pragma("unroll") \
    for (int it = 0; it < 4; it++) { \
        int ch = it * 256 + tid, row = ch >> 3, off = ch & 7; \
        int pr = srow[row]; \
        const float* src = (pr >= 0) ? g_act + (size_t)pr * H_EXP + k0 + off * 4 : g_act; \
        cpa16z(ab + row * (ASW * 4) + off * 16, src, (pr >= 0) ? 16 : 0); \
    } \
    uint32_t bb = smB + (BUF_) * (DN_BBUF * 4); \
    _Pragma("unroll") \
    for (int it = 0; it < 4; it++) { \
        int ch = it * 256 + tid, k = ch >> 5, off = ch & 31; \
        cpa16(bb + k * (DBSW * 4) + off * 16, \
              wde + (size_t)(k0 + k) * D_EMB + n0 + off * 4); \
    } }

    const int S = H_EXP / KS;   // 64
    DN_LOAD(0, 0)
    CP_COMMIT();

#pragma unroll 1
    for (int s = 0; s < S; s++) {
        if (s + 1 < S) { DN_LOAD(s + 1, (s + 1) & 1) CP_COMMIT(); CP_WAIT1(); }
        else           { CP_WAIT0(); }
        __syncthreads();

        const float* aT = fA + (s & 1) * A_BUF;
        const float* bT = fB + (s & 1) * DN_BBUF;
#pragma unroll
        for (int kb = 0; kb < 4; kb++) {
            int c = kb * 8 + (lane & 3);
            uint32_t af[2][4];
#pragma unroll
            for (int ma = 0; ma < 2; ma++) {
                int r = wm * 32 + ma * 16 + (lane >> 2);
                af[ma][0] = tf32c(aT[r * ASW + c]);
                af[ma][1] = tf32c(aT[(r + 8) * ASW + c]);
                af[ma][2] = tf32c(aT[r * ASW + c + 4]);
                af[ma][3] = tf32c(aT[(r + 8) * ASW + c + 4]);
            }
#pragma unroll
            for (int na = 0; na < 8; na++) {
                int n = wn * 64 + na * 8 + (lane >> 2);
                uint32_t b0 = tf32c(bT[c * DBSW + n]);
                uint32_t b1 = tf32c(bT[(c + 4) * DBSW + n]);
#pragma unroll
                for (int ma = 0; ma < 2; ma++)
                    mma_tf32(acc[ma][na], af[ma][0], af[ma][1], af[ma][2], af[ma][3], b0, b1);
            }
        }
        __syncthreads();
    }

#pragma unroll
    for (int ma = 0; ma < 2; ma++) {
        int row0 = wm * 32 + ma * 16 + (lane >> 2);
#pragma unroll
        for (int half = 0; half < 2; half++) {
            int row = row0 + half * 8;
            int pr = srow[row];
            if (pr < 0) continue;
            float w = swt[row];
            float* dst = g_y + (size_t)pr * D_EMB + n0;
#pragma unroll
            for (int na = 0; na < 8; na++) {
                float v0 = acc[ma][na][half * 2 + 0] * w;
                float v1 = acc[ma][na][half * 2 + 1] * w;
                int col = wn * 64 + na * 8 + (lane & 3) * 2;
                *(float2*)(dst + col) = make_float2(v0, v1);
            }
        }
    }
#undef DN_LOAD
}

// ---------------- combine ----------------
__global__ void combine_kernel(float* __restrict__ out) {
    size_t i = (size_t)blockIdx.x * blockDim.x + threadIdx.x;
    int t = (int)(i >> 10);
    int d = (int)(i & 1023);
    out[i] = g_y[(size_t)t * 2048 + d] + g_y[(size_t)t * 2048 + 1024 + d];
}

// ---------------- launch ----------------
extern "C" void kernel_launch(void* const* d_in, const int* in_sizes, int n_in,
                              void* d_out, int out_size) {
    const float* x     = (const float*)d_in[0];
    const float* gin   = (const float*)d_in[1];
    const float* gk    = (const float*)d_in[2];
    const float* scale = (const float*)d_in[3];
    const float* wg    = (const float*)d_in[4];
    const float* wu    = (const float*)d_in[5];
    const float* wd    = (const float*)d_in[6];
    float* out         = (float*)d_out;

    cudaFuncSetAttribute(moe_up_mma,   cudaFuncAttributeMaxDynamicSharedMemorySize, UP_SMEM);
    cudaFuncSetAttribute(moe_down_mma, cudaFuncAttributeMaxDynamicSharedMemorySize, DN_SMEM);

    zero_counts_kernel<<<1, 32>>>();
    gating_kernel<<<T_TOK, 256>>>(gin, gk, scale);

    dim3 g1(H_EXP / 64, T_TOK / 128, N_EXP);    // 32 x 16 x 8
    moe_up_mma<<<g1, 256, UP_SMEM>>>(x, wg, wu);

    dim3 g2(D_EMB / 128, T_TOK / 128, N_EXP);   // 8 x 16 x 8
    moe_down_mma<<<g2, 256, DN_SMEM>>>(wd);

    combine_kernel<<<(T_TOK * D_EMB) / 256, 256>>>(out);
}

// round 12
// speedup vs baseline: 2.0940x; 1.0020x over previous
#include <cuda_runtime.h>
#include <cstdint>
#include <math.h>

#define T_TOK 2048
#define D_EMB 1024
#define H_EXP 2048
#define N_EXP 8

#define KS 32              // fp32 K per stage
#define ASW 36             // A smem row stride in words (32 data + 4 pad): banks 4r+c -> conflict-free
#define A_BUF (128 * ASW)  // words
#define DBSW 136           // down B row stride ([k][n128], 8k+n banks)
#define DN_BBUF (32 * DBSW)
#define UBSW 72            // up B row stride ([k][n64], 8k+n banks)
#define UP_BBUF (32 * UBSW)
#define DN_SMEM ((2 * A_BUF + 2 * DN_BBUF) * 4)   // 71680 B
#define UP_SMEM ((2 * A_BUF + 4 * UP_BBUF) * 4)   // 73728 B

// ---------------- device scratch (static, allocation-free) ----------------
__device__ __align__(16) int   g_cnt[N_EXP];
__device__ __align__(16) int   g_pair[N_EXP * T_TOK];
__device__ __align__(16) float g_wt [N_EXP * T_TOK];
__device__ __align__(16) float g_act[(size_t)T_TOK * 2 * H_EXP]; // 32 MB
__device__ __align__(16) float g_y  [(size_t)T_TOK * 2 * D_EMB]; // 16 MB

// ---------------- helpers ----------------
__device__ __forceinline__ float gelu_tanh(float x) {
    float x3 = x * x * x;
    float inner = 0.7978845608028654f * (x + 0.044715f * x3);
    return 0.5f * x * (1.0f + tanhf(inner));
}
__device__ __forceinline__ uint32_t tf32c(float x) {
    uint32_t r;
    asm("cvt.rna.tf32.f32 %0, %1;" : "=r"(r) : "f"(x));
    return r;
}
__device__ __forceinline__ void mma_tf32(float* c,
                                         uint32_t a0, uint32_t a1, uint32_t a2, uint32_t a3,
                                         uint32_t b0, uint32_t b1) {
    asm volatile(
        "mma.sync.aligned.m16n8k8.row.col.f32.tf32.tf32.f32 "
        "{%0,%1,%2,%3}, {%4,%5,%6,%7}, {%8,%9}, {%0,%1,%2,%3};"
        : "+f"(c[0]), "+f"(c[1]), "+f"(c[2]), "+f"(c[3])
        : "r"(a0), "r"(a1), "r"(a2), "r"(a3), "r"(b0), "r"(b1));
}
__device__ __forceinline__ void cpa16(uint32_t dst, const void* src) {
    asm volatile("cp.async.cg.shared.global [%0], [%1], 16;" :: "r"(dst), "l"(src));
}
__device__ __forceinline__ void cpa16z(uint32_t dst, const void* src, int sz) {
    asm volatile("cp.async.cg.shared.global [%0], [%1], 16, %2;" :: "r"(dst), "l"(src), "r"(sz));
}
#define CP_COMMIT() asm volatile("cp.async.commit_group;")
#define CP_WAIT1()  asm volatile("cp.async.wait_group 1;")
#define CP_WAIT0()  asm volatile("cp.async.wait_group 0;")

// ---------------- small kernels ----------------
__global__ void zero_counts_kernel() {
    if (threadIdx.x < N_EXP) g_cnt[threadIdx.x] = 0;
}

__global__ void gating_kernel(const float* __restrict__ gin,
                              const float* __restrict__ gk,
                              const float* __restrict__ scale) {
    int t = blockIdx.x;
    const float* row = gin + (size_t)t * D_EMB;
    float p[N_EXP];
#pragma unroll
    for (int e = 0; e < N_EXP; e++) p[e] = 0.0f;
    for (int i = threadIdx.x; i < D_EMB; i += blockDim.x) {
        float v = row[i];
#pragma unroll
        for (int e = 0; e < N_EXP; e++) p[e] += v * gk[i * N_EXP + e];
    }
#pragma unroll
    for (int e = 0; e < N_EXP; e++) {
#pragma unroll
        for (int off = 16; off > 0; off >>= 1)
            p[e] += __shfl_down_sync(0xffffffffu, p[e], off);
    }
    __shared__ float sm[8][N_EXP];
    int warp = threadIdx.x >> 5, lane = threadIdx.x & 31;
    if (lane == 0) {
#pragma unroll
        for (int e = 0; e < N_EXP; e++) sm[warp][e] = p[e];
    }
    __syncthreads();
    if (threadIdx.x == 0) {
        float logit[N_EXP];
        int nw = blockDim.x >> 5;
#pragma unroll
        for (int e = 0; e < N_EXP; e++) {
            float s = 0.0f;
            for (int w = 0; w < nw; w++) s += sm[w][e];
            logit[e] = s;
        }
        int e0 = 0;
#pragma unroll
        for (int e = 1; e < N_EXP; e++) if (logit[e] > logit[e0]) e0 = e;
        int e1 = (e0 == 0) ? 1 : 0;
#pragma unroll
        for (int e = 0; e < N_EXP; e++)
            if (e != e0 && logit[e] > logit[e1]) e1 = e;
        float w0 = (1.0f / (1.0f + expf(-logit[e0]))) * scale[e0];
        float w1 = (1.0f / (1.0f + expf(-logit[e1]))) * scale[e1];
        int s0 = atomicAdd(&g_cnt[e0], 1);
        g_pair[e0 * T_TOK + s0] = t * 2 + 0; g_wt[e0 * T_TOK + s0] = w0;
        int s1 = atomicAdd(&g_cnt[e1], 1);
        g_pair[e1 * T_TOK + s1] = t * 2 + 1; g_wt[e1 * T_TOK + s1] = w1;
    }
}

// ---------------- pass 1: TF32 fused gate/up (cp.async, M128 x N64(x2)) ----------------
// 8 warps: wm = wid&3 (M), wn = wid>>2 (N). warp tile 32 x 32 per matrix.
__global__ __launch_bounds__(256, 2)
void moe_up_mma(const float* __restrict__ x,
                const float* __restrict__ wg,
                const float* __restrict__ wu) {
    int e = blockIdx.z;
    int cnt = g_cnt[e];
    int m0 = blockIdx.y * 128;
    if (m0 >= cnt) return;
    int n0 = blockIdx.x * 64;

    extern __shared__ float dyn[];
    float* fA  = dyn;                        // 2 * A_BUF
    float* fBg = dyn + 2 * A_BUF;            // 2 * UP_BBUF
    float* fBu = fBg + 2 * UP_BBUF;          // 2 * UP_BBUF
    __shared__ int srow[128];

    int tid = threadIdx.x, lane = tid & 31, wid = tid >> 5;
    int wm = wid & 3, wn = wid >> 2;

    if (tid < 128) {
        int s = m0 + tid;
        srow[tid] = (s < cnt) ? g_pair[e * T_TOK + s] : -1;
    }
    __syncthreads();

    uint32_t smA  = (uint32_t)__cvta_generic_to_shared(fA);
    uint32_t smBg = (uint32_t)__cvta_generic_to_shared(fBg);
    uint32_t smBu = (uint32_t)__cvta_generic_to_shared(fBu);

    const float* wge = wg + (size_t)e * D_EMB * H_EXP;
    const float* wue = wu + (size_t)e * D_EMB * H_EXP;

    float acc_g[2][4][4], acc_u[2][4][4];
#pragma unroll
    for (int i = 0; i < 2; i++)
#pragma unroll
        for (int j = 0; j < 4; j++)
#pragma unroll
            for (int q = 0; q < 4; q++) { acc_g[i][j][q] = 0.f; acc_u[i][j][q] = 0.f; }

#define UP_LOAD(S_, BUF_) { \
    int k0 = (S_) * KS; \
    uint32_t ab = smA + (BUF_) * (A_BUF * 4); \
    _Pragma("unroll") \
    for (int it = 0; it < 4; it++) { \
        int ch = it * 256 + tid, row = ch >> 3, off = ch & 7; \
        int pr = srow[row]; \
        const float* src = (pr >= 0) ? x + (size_t)(pr >> 1) * D_EMB + k0 + off * 4 : x; \
        cpa16z(ab + row * (ASW * 4) + off * 16, src, (pr >= 0) ? 16 : 0); \
    } \
    uint32_t gb = smBg + (BUF_) * (UP_BBUF * 4); \
    uint32_t ub = smBu + (BUF_) * (UP_BBUF * 4); \
    _Pragma("unroll") \
    for (int it = 0; it < 4; it++) { \
        int ch = it * 256 + tid; \
        int mat = ch >> 9, k = (ch >> 4) & 31, off = ch & 15; \
        const float* src = (mat ? wue : wge) + (size_t)(k0 + k) * H_EXP + n0 + off * 4; \
        cpa16((mat ? ub : gb) + k * (UBSW * 4) + off * 16, src); \
    } }

    const int S = D_EMB / KS;   // 32
    UP_LOAD(0, 0)
    CP_COMMIT();

#pragma unroll 1
    for (int s = 0; s < S; s++) {
        if (s + 1 < S) { UP_LOAD(s + 1, (s + 1) & 1) CP_COMMIT(); CP_WAIT1(); }
        else           { CP_WAIT0(); }
        __syncthreads();

        const float* aT = fA  + (s & 1) * A_BUF;
        const float* gT = fBg + (s & 1) * UP_BBUF;
        const float* uT = fBu + (s & 1) * UP_BBUF;
#pragma unroll
        for (int kb = 0; kb < 4; kb++) {
            int c = kb * 8 + (lane & 3);
            uint32_t af[2][4];
#pragma unroll
            for (int ma = 0; ma < 2; ma++) {
                int r = wm * 32 + ma * 16 + (lane >> 2);
                af[ma][0] = tf32c(aT[r * ASW + c]);
                af[ma][1] = tf32c(aT[(r + 8) * ASW + c]);
                af[ma][2] = tf32c(aT[r * ASW + c + 4]);
                af[ma][3] = tf32c(aT[(r + 8) * ASW + c + 4]);
            }
#pragma unroll
            for (int na = 0; na < 4; na++) {
                int n = wn * 32 + na * 8 + (lane >> 2);
                uint32_t bg0 = tf32c(gT[c * UBSW + n]);
                uint32_t bg1 = tf32c(gT[(c + 4) * UBSW + n]);
                uint32_t bu0 = tf32c(uT[c * UBSW + n]);
                uint32_t bu1 = tf32c(uT[(c + 4) * UBSW + n]);
#pragma unroll
                for (int ma = 0; ma < 2; ma++) {
                    mma_tf32(acc_g[ma][na], af[ma][0], af[ma][1], af[ma][2], af[ma][3], bg0, bg1);
                    mma_tf32(acc_u[ma][na], af[ma][0], af[ma][1], af[ma][2], af[ma][3], bu0, bu1);
                }
            }
        }
        __syncthreads();
    }

    // epilogue: act = gelu(gate) * up
#pragma unroll
    for (int ma = 0; ma < 2; ma++) {
        int row0 = wm * 32 + ma * 16 + (lane >> 2);
#pragma unroll
        for (int half = 0; half < 2; half++) {
            int row = row0 + half * 8;
            int pr = srow[row];
            if (pr < 0) continue;
            float* dst = g_act + (size_t)pr * H_EXP + n0;
#pragma unroll
            for (int na = 0; na < 4; na++) {
                float g0 = acc_g[ma][na][half * 2 + 0], g1 = acc_g[ma][na][half * 2 + 1];
                float u0 = acc_u[ma][na][half * 2 + 0], u1 = acc_u[ma][na][half * 2 + 1];
                int col = wn * 32 + na * 8 + (lane & 3) * 2;
                *(float2*)(dst + col) = make_float2(gelu_tanh(g0) * u0, gelu_tanh(g1) * u1);
            }
        }
    }
#undef UP_LOAD
}

// ---------------- pass 2: TF32 down-proj (cp.async, M128 x N128) ----------------
// 8 warps: wm = wid&3 (M), wn = wid>>2 (N). warp tile 32 x 64.
__global__ __launch_bounds__(256, 2)
void moe_down_mma(const float* __restrict__ wd) {
    int e = blockIdx.z;
    int cnt = g_cnt[e];
    int m0 = blockIdx.y * 128;
    if (m0 >= cnt) return;
    int n0 = blockIdx.x * 128;

    extern __shared__ float dyn[];
    float* fA = dyn;                 // 2 * A_BUF
    float* fB = dyn + 2 * A_BUF;     // 2 * DN_BBUF
    __shared__ int   srow[128];
    __shared__ float swt[128];

    int tid = threadIdx.x, lane = tid & 31, wid = tid >> 5;
    int wm = wid & 3, wn = wid >> 2;

    if (tid < 128) {
        int s = m0 + tid;
        if (s < cnt) { srow[tid] = g_pair[e * T_TOK + s]; swt[tid] = g_wt[e * T_TOK + s]; }
        else         { srow[tid] = -1; swt[tid] = 0.f; }
    }
    __syncthreads();

    uint32_t smA = (uint32_t)__cvta_generic_to_shared(fA);
    uint32_t smB = (uint32_t)__cvta_generic_to_shared(fB);

    const float* wde = wd + (size_t)e * H_EXP * D_EMB;

    float acc[2][8][4];
#pragma unroll
    for (int i = 0; i < 2; i++)
#pragma unroll
        for (int j = 0; j < 8; j++)
#pragma unroll
            for (int q = 0; q < 4; q++) acc[i][j][q] = 0.f;

#define DN_LOAD(S_, BUF_) { \
    int k0 = (S_) * KS; \
    uint32_t ab = smA + (BUF_) * (A_BUF * 4); \
    _Pragma("unroll") \
    for (int it = 0; it < 4; it++) { \
        int ch = it * 256 + tid, row = ch >> 3, off = ch & 7; \
        int pr = srow[row]; \
        const float* src = (pr >= 0) ? g_act + (size_t)pr * H_EXP + k0 + off * 4 : g_act; \
        cpa16z(ab + row * (ASW * 4) + off * 16, src, (pr >= 0) ? 16 : 0); \
    } \
    uint32_t bb = smB + (BUF_) * (DN_BBUF * 4); \
    _Pragma("unroll") \
    for (int it = 0; it < 4; it++) { \
        int ch = it * 256 + tid, k = ch >> 5, off = ch & 31; \
        cpa16(bb + k * (DBSW * 4) + off * 16, \
              wde + (size_t)(k0 + k) * D_EMB + n0 + off * 4); \
    } }

    const int S = H_EXP / KS;   // 64
    DN_LOAD(0, 0)
    CP_COMMIT();

#pragma unroll 1
    for (int s = 0; s < S; s++) {
        if (s + 1 < S) { DN_LOAD(s + 1, (s + 1) & 1) CP_COMMIT(); CP_WAIT1(); }
        else           { CP_WAIT0(); }
        __syncthreads();

        const float* aT = fA + (s & 1) * A_BUF;
        const float* bT = fB + (s & 1) * DN_BBUF;
#pragma unroll
        for (int kb = 0; kb < 4; kb++) {
            int c = kb * 8 + (lane & 3);
            uint32_t af[2][4];
#pragma unroll
            for (int ma = 0; ma < 2; ma++) {
                int r = wm * 32 + ma * 16 + (lane >> 2);
                af[ma][0] = tf32c(aT[r * ASW + c]);
                af[ma][1] = tf32c(aT[(r + 8) * ASW + c]);
                af[ma][2] = tf32c(aT[r * ASW + c + 4]);
                af[ma][3] = tf32c(aT[(r + 8) * ASW + c + 4]);
            }
#pragma unroll
            for (int na = 0; na < 8; na++) {
                int n = wn * 64 + na * 8 + (lane >> 2);
                uint32_t b0 = tf32c(bT[c * DBSW + n]);
                uint32_t b1 = tf32c(bT[(c + 4) * DBSW + n]);
#pragma unroll
                for (int ma = 0; ma < 2; ma++)
                    mma_tf32(acc[ma][na], af[ma][0], af[ma][1], af[ma][2], af[ma][3], b0, b1);
            }
        }
        __syncthreads();
    }

#pragma unroll
    for (int ma = 0; ma < 2; ma++) {
        int row0 = wm * 32 + ma * 16 + (lane >> 2);
#pragma unroll
        for (int half = 0; half < 2; half++) {
            int row = row0 + half * 8;
            int pr = srow[row];
            if (pr < 0) continue;
            float w = swt[row];
            float* dst = g_y + (size_t)pr * D_EMB + n0;
#pragma unroll
            for (int na = 0; na < 8; na++) {
                float v0 = acc[ma][na][half * 2 + 0] * w;
                float v1 = acc[ma][na][half * 2 + 1] * w;
                int col = wn * 64 + na * 8 + (lane & 3) * 2;
                *(float2*)(dst + col) = make_float2(v0, v1);
            }
        }
    }
#undef DN_LOAD
}

// ---------------- combine ----------------
__global__ void combine_kernel(float* __restrict__ out) {
    size_t i = (size_t)blockIdx.x * blockDim.x + threadIdx.x;
    int t = (int)(i >> 10);
    int d = (int)(i & 1023);
    out[i] = g_y[(size_t)t * 2048 + d] + g_y[(size_t)t * 2048 + 1024 + d];
}

// ---------------- launch ----------------
extern "C" void kernel_launch(void* const* d_in, const int* in_sizes, int n_in,
                              void* d_out, int out_size) {
    const float* x     = (const float*)d_in[0];
    const float* gin   = (const float*)d_in[1];
    const float* gk    = (const float*)d_in[2];
    const float* scale = (const float*)d_in[3];
    const float* wg    = (const float*)d_in[4];
    const float* wu    = (const float*)d_in[5];
    const float* wd    = (const float*)d_in[6];
    float* out         = (float*)d_out;

    cudaFuncSetAttribute(moe_up_mma,   cudaFuncAttributeMaxDynamicSharedMemorySize, UP_SMEM);
    cudaFuncSetAttribute(moe_down_mma, cudaFuncAttributeMaxDynamicSharedMemorySize, DN_SMEM);

    zero_counts_kernel<<<1, 32>>>();
    gating_kernel<<<T_TOK, 256>>>(gin, gk, scale);

    dim3 g1(H_EXP / 64, T_TOK / 128, N_EXP);    // 32 x 16 x 8
    moe_up_mma<<<g1, 256, UP_SMEM>>>(x, wg, wu);

    dim3 g2(D_EMB / 128, T_TOK / 128, N_EXP);   // 8 x 16 x 8
    moe_down_mma<<<g2, 256, DN_SMEM>>>(wd);

    combine_kernel<<<(T_TOK * D_EMB) / 256, 256>>>(out);
}